// round 10
// baseline (speedup 1.0000x reference)
#include <cuda_runtime.h>
#include <cuda_bf16.h>
#include <cstdint>

#define NMAXP 10240          // padded row capacity (N=10000 -> 79*128=10112)
#define D 256
#define EMAX 200000

// ---------------- scratch (no allocation allowed) ----------------
__device__ float g_xl[NMAXP * D];
__device__ float g_xr[NMAXP * D];
__device__ float g_agg[NMAXP * D];
__device__ float g_ql[NMAXP];            // att . xl[i]
__device__ __align__(16) float g_colsum[D];
__device__ __align__(16) float g_colsumsq[D];
__device__ int   g_is32;
__device__ int   g_total;
// CSR by destination (unordered base allocation)
__device__ int g_deg[NMAXP];
__device__ int g_off[NMAXP];
__device__ int g_cur[NMAXP];
__device__ int g_csr_src[EMAX];
// bf16 split operands
__device__ __nv_bfloat16 g_ah[NMAXP * D];
__device__ __nv_bfloat16 g_al[NMAXP * D];
__device__ __nv_bfloat16 g_bh[512 * D];   // B[n][k] = W[k][n], n in [0,512)
__device__ __nv_bfloat16 g_bl[512 * D];

// ================= helpers =========================================
__device__ __forceinline__ uint32_t smem_u32(const void* p) {
    uint32_t a;
    asm("{ .reg .u64 t; cvta.to.shared.u64 t, %1; cvt.u32.u64 %0, t; }" : "=r"(a) : "l"(p));
    return a;
}
__device__ __forceinline__ void ldsm_x4(uint32_t& r0, uint32_t& r1, uint32_t& r2,
                                        uint32_t& r3, uint32_t a) {
    asm volatile("ldmatrix.sync.aligned.m8n8.x4.shared.b16 {%0,%1,%2,%3}, [%4];"
                 : "=r"(r0), "=r"(r1), "=r"(r2), "=r"(r3) : "r"(a));
}
__device__ __forceinline__ void mma_bf16(float* d, const uint32_t* a, const uint32_t* b) {
    asm volatile(
        "mma.sync.aligned.m16n8k16.row.col.f32.bf16.bf16.f32 "
        "{%0,%1,%2,%3},{%4,%5,%6,%7},{%8,%9},{%0,%1,%2,%3};"
        : "+f"(d[0]), "+f"(d[1]), "+f"(d[2]), "+f"(d[3])
        : "r"(a[0]), "r"(a[1]), "r"(a[2]), "r"(a[3]), "r"(b[0]), "r"(b[1]));
}
__device__ __forceinline__ void cpasync16(uint32_t dst, const void* src) {
    asm volatile("{ .reg .u64 g; cvta.to.global.u64 g, %1;"
                 "  cp.async.cg.shared.global [%0], [g], 16; }"
                 :: "r"(dst), "l"(src) : "memory");
}

// ---------------- init: zero counters + detect dtype ----------------
__global__ void k_init(const long long* ei, int E, int N) {
    int tid = blockIdx.x * blockDim.x + threadIdx.x;
    int stride = gridDim.x * blockDim.x;
    for (int i = tid; i < N; i += stride) g_deg[i] = 0;
    if (blockIdx.x == 0) {
        if (threadIdx.x < D) {
            g_colsum[threadIdx.x] = 0.f;
            g_colsumsq[threadIdx.x] = 0.f;
        }
        if (threadIdx.x == 0) g_total = 0;
    }
    if (blockIdx.x == 1) {
        int bad = 0;
        int lim = E < 2048 ? E : 2048;
        for (int i = threadIdx.x; i < lim; i += blockDim.x) {
            long long v = ei[i];
            if (v < 0 || v >= (long long)N) bad = 1;
        }
        int any = __syncthreads_or(bad);
        if (threadIdx.x == 0) g_is32 = any ? 1 : 0;
    }
}

// ---------------- CSR build: count (2 edges/thread) -----------------
__global__ void k_count(const void* __restrict__ ei, int E) {
    int i0 = (blockIdx.x * blockDim.x + threadIdx.x) * 2;
    if (i0 >= E) return;
    int is32 = g_is32;
    int m = min(2, E - i0);
    int d[2];
#pragma unroll
    for (int j = 0; j < 2; j++)
        if (j < m)
            d[j] = is32 ? __ldg((const int*)ei + E + i0 + j)
                        : (int)__ldg((const long long*)ei + E + i0 + j);
#pragma unroll
    for (int j = 0; j < 2; j++)
        if (j < m) atomicAdd(&g_deg[d[j]], 1);
}

// ---------------- CSR build: unordered base allocation ---------------
__global__ void k_alloc(int N) {
    int i = blockIdx.x * blockDim.x + threadIdx.x;
    int lane = threadIdx.x & 31;
    int d = (i < N) ? g_deg[i] : 0;
    int p = d;
#pragma unroll
    for (int o = 1; o < 32; o <<= 1) {
        int t = __shfl_up_sync(0xffffffffu, p, o);
        if (lane >= o) p += t;
    }
    int total = __shfl_sync(0xffffffffu, p, 31);
    int base = 0;
    if (lane == 0) base = atomicAdd(&g_total, total);
    base = __shfl_sync(0xffffffffu, base, 0);
    int off = base + p - d;
    if (i < N) {
        g_off[i] = off;
        g_cur[i] = off;
    }
}

// ---------------- CSR build: fill (2 edges/thread) -------------------
__global__ void k_fill(const void* __restrict__ ei, int E) {
    int i0 = (blockIdx.x * blockDim.x + threadIdx.x) * 2;
    if (i0 >= E) return;
    int is32 = g_is32;
    int m = min(2, E - i0);
    int s[2], d[2], pos[2];
#pragma unroll
    for (int j = 0; j < 2; j++) {
        if (j < m) {
            if (is32) {
                s[j] = __ldg((const int*)ei + i0 + j);
                d[j] = __ldg((const int*)ei + E + i0 + j);
            } else {
                s[j] = (int)__ldg((const long long*)ei + i0 + j);
                d[j] = (int)__ldg((const long long*)ei + E + i0 + j);
            }
        }
    }
#pragma unroll
    for (int j = 0; j < 2; j++)
        if (j < m) pos[j] = atomicAdd(&g_cur[d[j]], 1);
#pragma unroll
    for (int j = 0; j < 2; j++)
        if (j < m) g_csr_src[pos[j]] = s[j];
}

// ---------------- fused conversions: W transpose + x hi/lo split ------
// Also zeroes g_ql (ordered before k_hmma on the same stream).
__global__ void k_conv(const float* __restrict__ x, const float* __restrict__ Wl,
                       const float* __restrict__ Wr, int N, int NPAD) {
    int zt = blockIdx.x * 256 + threadIdx.x;
    if (zt < NMAXP) g_ql[zt] = 0.f;
    if (blockIdx.x < 128) {
        __shared__ __nv_bfloat16 sh[32][33];
        __shared__ __nv_bfloat16 sl[32][33];
        int n0 = (blockIdx.x & 15) * 32;
        int k0 = (blockIdx.x >> 4) * 32;
        int tid = threadIdx.x;
        int c = tid & 31;
        int r = tid >> 5;
#pragma unroll
        for (int i = 0; i < 4; i++) {
            int k = r + i * 8;
            int n = n0 + c;
            float v = (n < 256) ? Wl[(size_t)(k0 + k) * 256 + n]
                                : Wr[(size_t)(k0 + k) * 256 + (n - 256)];
            __nv_bfloat16 h = __float2bfloat16(v);
            sh[k][c] = h;
            sl[k][c] = __float2bfloat16(v - __bfloat162float(h));
        }
        __syncthreads();
        int nn = tid >> 4;
        int kk = (tid & 15) * 2;
#pragma unroll
        for (int i = 0; i < 2; i++) {
            int nl = nn + i * 16;
            int n = n0 + nl;
            *(__nv_bfloat162*)&g_bh[(size_t)n * D + k0 + kk] = __nv_bfloat162(sh[kk][nl], sh[kk + 1][nl]);
            *(__nv_bfloat162*)&g_bl[(size_t)n * D + k0 + kk] = __nv_bfloat162(sl[kk][nl], sl[kk + 1][nl]);
        }
    } else {
        int gid = (blockIdx.x - 128) * 256 + threadIdx.x;
        int total = NPAD * (D / 4);
        if (gid >= total) return;
        int base = gid * 4;
        int r = base >> 8;
        float4 v = (r < N) ? *(const float4*)(x + base) : make_float4(0.f, 0.f, 0.f, 0.f);
        __nv_bfloat16 h0 = __float2bfloat16(v.x), h1 = __float2bfloat16(v.y);
        __nv_bfloat16 h2 = __float2bfloat16(v.z), h3 = __float2bfloat16(v.w);
        __nv_bfloat16 l0 = __float2bfloat16(v.x - __bfloat162float(h0));
        __nv_bfloat16 l1 = __float2bfloat16(v.y - __bfloat162float(h1));
        __nv_bfloat16 l2 = __float2bfloat16(v.z - __bfloat162float(h2));
        __nv_bfloat16 l3 = __float2bfloat16(v.w - __bfloat162float(h3));
        __nv_bfloat162* ph = (__nv_bfloat162*)(g_ah + base);
        __nv_bfloat162* pl = (__nv_bfloat162*)(g_al + base);
        ph[0] = __nv_bfloat162(h0, h1); ph[1] = __nv_bfloat162(h2, h3);
        pl[0] = __nv_bfloat162(l0, l1); pl[1] = __nv_bfloat162(l2, l3);
    }
}

// ---------------- HMMA 3xBF16 fused GEMM (+ fused ql dot) ------------
#define SMSTRIDE 144
#define ASZ (128 * SMSTRIDE)
#define BSZ (256 * SMSTRIDE)
#define STG (2 * ASZ + 2 * BSZ)
#define OFF_AH 0
#define OFF_AL ASZ
#define OFF_BH (2 * ASZ)
#define OFF_BL (2 * ASZ + BSZ)

__global__ void __launch_bounds__(512, 1)
k_hmma(const float* __restrict__ bl, const float* __restrict__ br,
       const float* __restrict__ att, int N) {
    extern __shared__ char sm[];
    uint32_t sb = smem_u32(sm);
    const int tid = threadIdx.x, lane = tid & 31, warp = tid >> 5;
    const int wm = warp >> 2, wn = warp & 3;
    const int row0 = blockIdx.y * 128;
    const int ncol0 = blockIdx.x * 256;

    float acc[2][8][4];
#pragma unroll
    for (int mt = 0; mt < 2; mt++)
#pragma unroll
        for (int nt = 0; nt < 8; nt++)
#pragma unroll
            for (int i = 0; i < 4; i++) acc[mt][nt][i] = 0.f;

    auto issue = [&](int c) {
        uint32_t s0 = sb + (c & 1) * STG;
        int kc = c * 64;
#pragma unroll
        for (int i = 0; i < 12; i++) {
            int idx = tid + i * 512;
            int r = idx >> 3, g = idx & 7;
            if (r < 256) {
                int ar = r & 127;
                uint32_t dst = s0 + ((r < 128) ? OFF_AH : OFF_AL)
                             + (uint32_t)(ar * SMSTRIDE + g * 16);
                const __nv_bfloat16* srcb = (r < 128) ? g_ah : g_al;
                cpasync16(dst, srcb + (size_t)(row0 + ar) * D + kc + g * 8);
            } else {
                int br_ = (r - 256) & 255;
                uint32_t dst = s0 + ((r < 512) ? OFF_BH : OFF_BL)
                             + (uint32_t)(br_ * SMSTRIDE + g * 16);
                const __nv_bfloat16* srcb = (r < 512) ? g_bh : g_bl;
                cpasync16(dst, srcb + (size_t)(ncol0 + br_) * D + kc + g * 8);
            }
        }
        asm volatile("cp.async.commit_group;" ::: "memory");
    };

    issue(0);
    for (int c = 0; c < 4; c++) {
        if (c < 3) {
            issue(c + 1);
            asm volatile("cp.async.wait_group 1;" ::: "memory");
        } else {
            asm volatile("cp.async.wait_group 0;" ::: "memory");
        }
        __syncthreads();

        uint32_t s0 = sb + (c & 1) * STG;
        uint32_t aoffB = (uint32_t)((wm * 32 + (lane & 15)) * SMSTRIDE + (lane >> 4) * 16);
        uint32_t nsel = (uint32_t)(lane >> 4);
        uint32_t nloc = (uint32_t)(lane & 7);
        uint32_t khalf = (uint32_t)((lane >> 3) & 1);

#pragma unroll
        for (int kt = 0; kt < 4; kt++) {
            uint32_t kb = kt * 32;
            uint32_t ah[2][4], al[2][4];
#pragma unroll
            for (int mt = 0; mt < 2; mt++) {
                uint32_t adr = s0 + OFF_AH + aoffB + mt * 16 * SMSTRIDE + kb;
                ldsm_x4(ah[mt][0], ah[mt][1], ah[mt][2], ah[mt][3], adr);
                ldsm_x4(al[mt][0], al[mt][1], al[mt][2], al[mt][3], adr + ASZ);
            }
            uint32_t bh[4][4], blo[4][4];
#pragma unroll
            for (int p = 0; p < 4; p++) {
                uint32_t n = (uint32_t)(wn * 64) + (2 * p + nsel) * 8 + nloc;
                uint32_t adr = s0 + OFF_BH + n * SMSTRIDE + kb + khalf * 16;
                ldsm_x4(bh[p][0], bh[p][1], bh[p][2], bh[p][3], adr);
                ldsm_x4(blo[p][0], blo[p][1], blo[p][2], blo[p][3], adr + BSZ);
            }
#pragma unroll
            for (int mt = 0; mt < 2; mt++)
#pragma unroll
                for (int nt = 0; nt < 8; nt++) {
                    const uint32_t* bhp = &bh[nt >> 1][(nt & 1) * 2];
                    const uint32_t* blp = &blo[nt >> 1][(nt & 1) * 2];
                    mma_bf16(acc[mt][nt], ah[mt], bhp);
                    mma_bf16(acc[mt][nt], al[mt], bhp);
                    mma_bf16(acc[mt][nt], ah[mt], blp);
                }
        }
        __syncthreads();
    }

    const float* bsel = (blockIdx.x == 0) ? bl : br;
    float* Cout = (blockIdx.x == 0) ? g_xl : g_xr;
    int colbase = wn * 64;
#pragma unroll
    for (int mt = 0; mt < 2; mt++) {
        int r0 = row0 + wm * 32 + mt * 16 + (lane >> 2);
        float d0 = 0.f, d1 = 0.f;      // att-dot partials for rows r0, r0+8
#pragma unroll
        for (int nt = 0; nt < 8; nt++) {
            int cc = colbase + nt * 8 + (lane & 3) * 2;
            float b0 = bsel[cc], b1 = bsel[cc + 1];
            float a0 = att[cc], a1 = att[cc + 1];
            float vx = acc[mt][nt][0] + b0, vy = acc[mt][nt][1] + b1;
            float vz = acc[mt][nt][2] + b0, vw = acc[mt][nt][3] + b1;
            d0 = fmaf(vx, a0, fmaf(vy, a1, d0));
            d1 = fmaf(vz, a0, fmaf(vw, a1, d1));
            if (r0 < N)     *(float2*)&Cout[(size_t)r0 * D + cc]       = make_float2(vx, vy);
            if (r0 + 8 < N) *(float2*)&Cout[(size_t)(r0 + 8) * D + cc] = make_float2(vz, vw);
        }
        if (blockIdx.x == 0) {
            // quad-reduce (lanes sharing the same row differ only in lane&3)
            d0 += __shfl_xor_sync(0xffffffffu, d0, 1);
            d0 += __shfl_xor_sync(0xffffffffu, d0, 2);
            d1 += __shfl_xor_sync(0xffffffffu, d1, 1);
            d1 += __shfl_xor_sync(0xffffffffu, d1, 2);
            if ((lane & 3) == 0) {
                if (r0 < N)     atomicAdd(&g_ql[r0], d0);
                if (r0 + 8 < N) atomicAdd(&g_ql[r0 + 8], d1);
            }
        }
    }
}

// ---------------- dst-centric aggregation + epilogue -----------------
// score = 0.6*(ql[src]+qr[dst]) + 0.4*sum att_d*|xl_d+xr_d|  (exact lrelu(0.2))
__global__ void __launch_bounds__(256, 5)
k_agg(const float* __restrict__ att, const float* __restrict__ bias,
      const float* __restrict__ du, int N) {
    __shared__ float s_sum[D];
    __shared__ float s_sq[D];
    int tid = threadIdx.x, warp = tid >> 5, lane = tid & 31;
    for (int i = tid; i < D; i += 256) { s_sum[i] = 0.f; s_sq[i] = 0.f; }
    __syncthreads();

    int dst = blockIdx.x * 8 + warp;
    if (dst < N) {
        const float4* xrd = (const float4*)(g_xr + (size_t)dst * D);
        float4 r0 = xrd[lane], r1 = xrd[lane + 32];
        float4 t0 = ((const float4*)att)[lane];
        float4 t1 = ((const float4*)att)[lane + 32];

        // qr[dst] = att . xr[dst], inline (one butterfly per dst)
        float qrd = t0.x * r0.x;
        qrd = fmaf(t0.y, r0.y, qrd); qrd = fmaf(t0.z, r0.z, qrd); qrd = fmaf(t0.w, r0.w, qrd);
        qrd = fmaf(t1.x, r1.x, qrd); qrd = fmaf(t1.y, r1.y, qrd);
        qrd = fmaf(t1.z, r1.z, qrd); qrd = fmaf(t1.w, r1.w, qrd);
#pragma unroll
        for (int o = 16; o; o >>= 1) qrd += __shfl_xor_sync(0xffffffffu, qrd, o);

        float4 acc0 = make_float4(0.f, 0.f, 0.f, 0.f);
        float4 acc1 = make_float4(0.f, 0.f, 0.f, 0.f);
        float den = 0.f;
        bool lo = lane < 16;

        int off = g_off[dst];
        int end = g_cur[dst];           // after k_fill, cur == off + deg

        for (int base = off - 1; base < end; base += 32) {
            int nsrc = -1;
            int idx = base + lane;
            if (idx >= off && idx < end) nsrc = g_csr_src[idx];
            else if (idx == off - 1) nsrc = dst;     // self-loop slot
            int m = min(32, end - base);
            int e = 0;
            for (; e + 1 < m; e += 2) {
                int s0i = __shfl_sync(0xffffffffu, nsrc, e);
                int s1i = __shfl_sync(0xffffffffu, nsrc, e + 1);
                float ql0 = __ldg(g_ql + s0i);
                float ql1 = __ldg(g_ql + s1i);
                const float4* x0 = (const float4*)(g_xl + (size_t)s0i * D);
                const float4* x1 = (const float4*)(g_xl + (size_t)s1i * D);
                float4 a00 = x0[lane], a01 = x0[lane + 32];
                float4 a10 = x1[lane], a11 = x1[lane + 32];
                float p0, p1;
                p0 = t0.x * fabsf(a00.x + r0.x);
                p0 = fmaf(t0.y, fabsf(a00.y + r0.y), p0);
                p0 = fmaf(t0.z, fabsf(a00.z + r0.z), p0);
                p0 = fmaf(t0.w, fabsf(a00.w + r0.w), p0);
                p0 = fmaf(t1.x, fabsf(a01.x + r1.x), p0);
                p0 = fmaf(t1.y, fabsf(a01.y + r1.y), p0);
                p0 = fmaf(t1.z, fabsf(a01.z + r1.z), p0);
                p0 = fmaf(t1.w, fabsf(a01.w + r1.w), p0);
                p1 = t0.x * fabsf(a10.x + r0.x);
                p1 = fmaf(t0.y, fabsf(a10.y + r0.y), p1);
                p1 = fmaf(t0.z, fabsf(a10.z + r0.z), p1);
                p1 = fmaf(t0.w, fabsf(a10.w + r0.w), p1);
                p1 = fmaf(t1.x, fabsf(a11.x + r1.x), p1);
                p1 = fmaf(t1.y, fabsf(a11.y + r1.y), p1);
                p1 = fmaf(t1.z, fabsf(a11.z + r1.z), p1);
                p1 = fmaf(t1.w, fabsf(a11.w + r1.w), p1);
                float c = lo ? p0 : p1;
                float dd = lo ? p1 : p0;
                c += __shfl_xor_sync(0xffffffffu, dd, 16);
                c += __shfl_xor_sync(0xffffffffu, c, 8);
                c += __shfl_xor_sync(0xffffffffu, c, 4);
                c += __shfl_xor_sync(0xffffffffu, c, 2);
                c += __shfl_xor_sync(0xffffffffu, c, 1);
                float qe = lo ? ql0 : ql1;
                c = __expf(fmaf(0.4f, c, 0.6f * (qe + qrd)));
                float ev0 = __shfl_sync(0xffffffffu, c, 0);
                float ev1 = __shfl_sync(0xffffffffu, c, 16);
                den += ev0 + ev1;
                acc0.x = fmaf(ev0, a00.x, fmaf(ev1, a10.x, acc0.x));
                acc0.y = fmaf(ev0, a00.y, fmaf(ev1, a10.y, acc0.y));
                acc0.z = fmaf(ev0, a00.z, fmaf(ev1, a10.z, acc0.z));
                acc0.w = fmaf(ev0, a00.w, fmaf(ev1, a10.w, acc0.w));
                acc1.x = fmaf(ev0, a01.x, fmaf(ev1, a11.x, acc1.x));
                acc1.y = fmaf(ev0, a01.y, fmaf(ev1, a11.y, acc1.y));
                acc1.z = fmaf(ev0, a01.z, fmaf(ev1, a11.z, acc1.z));
                acc1.w = fmaf(ev0, a01.w, fmaf(ev1, a11.w, acc1.w));
            }
            if (e < m) {
                int src = __shfl_sync(0xffffffffu, nsrc, e);
                float qls = __ldg(g_ql + src);
                const float4* xls = (const float4*)(g_xl + (size_t)src * D);
                float4 a0 = xls[lane], a1 = xls[lane + 32];
                float p;
                p = t0.x * fabsf(a0.x + r0.x);
                p = fmaf(t0.y, fabsf(a0.y + r0.y), p);
                p = fmaf(t0.z, fabsf(a0.z + r0.z), p);
                p = fmaf(t0.w, fabsf(a0.w + r0.w), p);
                p = fmaf(t1.x, fabsf(a1.x + r1.x), p);
                p = fmaf(t1.y, fabsf(a1.y + r1.y), p);
                p = fmaf(t1.z, fabsf(a1.z + r1.z), p);
                p = fmaf(t1.w, fabsf(a1.w + r1.w), p);
#pragma unroll
                for (int o = 16; o; o >>= 1) p += __shfl_xor_sync(0xffffffffu, p, o);
                float ev = __expf(fmaf(0.4f, p, 0.6f * (qls + qrd)));
                den += ev;
                acc0.x = fmaf(ev, a0.x, acc0.x); acc0.y = fmaf(ev, a0.y, acc0.y);
                acc0.z = fmaf(ev, a0.z, acc0.z); acc0.w = fmaf(ev, a0.w, acc0.w);
                acc1.x = fmaf(ev, a1.x, acc1.x); acc1.y = fmaf(ev, a1.y, acc1.y);
                acc1.z = fmaf(ev, a1.z, acc1.z); acc1.w = fmaf(ev, a1.w, acc1.w);
            }
        }

        float inv = 1.f / den;
        const float4* dup = (const float4*)(du + (size_t)dst * D);
        float4 u0 = dup[lane], u1 = dup[lane + 32];
        const float4* bp = (const float4*)bias;
        float4 b0 = bp[lane], b1 = bp[lane + 32];

        float4 v0, v1;
        v0.x = fmaxf(acc0.x * inv + b0.x, 0.f); v0.x = (u0.x >= 0.5f) ? v0.x * 2.f : 0.f;
        v0.y = fmaxf(acc0.y * inv + b0.y, 0.f); v0.y = (u0.y >= 0.5f) ? v0.y * 2.f : 0.f;
        v0.z = fmaxf(acc0.z * inv + b0.z, 0.f); v0.z = (u0.z >= 0.5f) ? v0.z * 2.f : 0.f;
        v0.w = fmaxf(acc0.w * inv + b0.w, 0.f); v0.w = (u0.w >= 0.5f) ? v0.w * 2.f : 0.f;
        v1.x = fmaxf(acc1.x * inv + b1.x, 0.f); v1.x = (u1.x >= 0.5f) ? v1.x * 2.f : 0.f;
        v1.y = fmaxf(acc1.y * inv + b1.y, 0.f); v1.y = (u1.y >= 0.5f) ? v1.y * 2.f : 0.f;
        v1.z = fmaxf(acc1.z * inv + b1.z, 0.f); v1.z = (u1.z >= 0.5f) ? v1.z * 2.f : 0.f;
        v1.w = fmaxf(acc1.w * inv + b1.w, 0.f); v1.w = (u1.w >= 0.5f) ? v1.w * 2.f : 0.f;

        float4* op = (float4*)(g_agg + (size_t)dst * D);
        op[lane] = v0; op[lane + 32] = v1;

        int c0 = lane * 4, c1 = 128 + lane * 4;
        atomicAdd(&s_sum[c0 + 0], v0.x); atomicAdd(&s_sq[c0 + 0], v0.x * v0.x);
        atomicAdd(&s_sum[c0 + 1], v0.y); atomicAdd(&s_sq[c0 + 1], v0.y * v0.y);
        atomicAdd(&s_sum[c0 + 2], v0.z); atomicAdd(&s_sq[c0 + 2], v0.z * v0.z);
        atomicAdd(&s_sum[c0 + 3], v0.w); atomicAdd(&s_sq[c0 + 3], v0.w * v0.w);
        atomicAdd(&s_sum[c1 + 0], v1.x); atomicAdd(&s_sq[c1 + 0], v1.x * v1.x);
        atomicAdd(&s_sum[c1 + 1], v1.y); atomicAdd(&s_sq[c1 + 1], v1.y * v1.y);
        atomicAdd(&s_sum[c1 + 2], v1.z); atomicAdd(&s_sq[c1 + 2], v1.z * v1.z);
        atomicAdd(&s_sum[c1 + 3], v1.w); atomicAdd(&s_sq[c1 + 3], v1.w * v1.w);
    }
    __syncthreads();
    atomicAdd(&g_colsum[tid], s_sum[tid]);
    atomicAdd(&g_colsumsq[tid], s_sq[tid]);
}

// ---------------- final BN normalize --------------------------------
__global__ void k_bnnorm(const float* __restrict__ gamma, const float* __restrict__ beta,
                         float* __restrict__ out, int N) {
    int d = threadIdx.x;
    float invN = 1.f / (float)N;
    float mean = g_colsum[d] * invN;
    float var = g_colsumsq[d] * invN - mean * mean;
    float inv = rsqrtf(var + 1e-5f);
    float ga = gamma[d], be = beta[d];
    for (int r = blockIdx.x; r < N; r += gridDim.x) {
        out[(size_t)r * D + d] = ga * (g_agg[(size_t)r * D + d] - mean) * inv + be;
    }
}

// ---------------- launch ---------------------------------------------
extern "C" void kernel_launch(void* const* d_in, const int* in_sizes, int n_in,
                              void* d_out, int out_size) {
    (void)n_in; (void)out_size;
    const float* x     = (const float*)d_in[0];
    const void*  ei    = d_in[1];
    const float* Wl    = (const float*)d_in[2];
    const float* bl    = (const float*)d_in[3];
    const float* Wr    = (const float*)d_in[4];
    const float* br    = (const float*)d_in[5];
    const float* att   = (const float*)d_in[6];
    const float* bias  = (const float*)d_in[7];
    const float* gamma = (const float*)d_in[8];
    const float* beta  = (const float*)d_in[9];
    const float* du    = (const float*)d_in[10];

    int N = in_sizes[0] / D;
    int E = in_sizes[1] / 2;
    int mrows = (N + 127) / 128;
    int NPAD = mrows * 128;

    const int SMEM_MMA = 2 * STG;   // 221184 bytes
    static cudaStream_t s2 = nullptr;
    static cudaEvent_t evFork = nullptr, evJoin = nullptr;
    if (!s2) {
        cudaFuncSetAttribute(k_hmma, cudaFuncAttributeMaxDynamicSharedMemorySize, SMEM_MMA);
        cudaStreamCreateWithFlags(&s2, cudaStreamNonBlocking);
        cudaEventCreateWithFlags(&evFork, cudaEventDisableTiming);
        cudaEventCreateWithFlags(&evJoin, cudaEventDisableTiming);
    }

    // ---- fork: CSR chain on s2, conv+GEMM chain on main ----
    cudaEventRecord(evFork, 0);
    cudaStreamWaitEvent(s2, evFork, 0);

    k_init<<<40, 256, 0, s2>>>((const long long*)ei, E, N);
    k_count<<<(E / 2 + 256) / 256, 256, 0, s2>>>(ei, E);
    k_alloc<<<(N + 255) / 256, 256, 0, s2>>>(N);
    k_fill<<<(E / 2 + 256) / 256, 256, 0, s2>>>(ei, E);
    cudaEventRecord(evJoin, s2);

    int xblocks = (NPAD * (D / 4) + 255) / 256;
    k_conv<<<128 + xblocks, 256>>>(x, Wl, Wr, N, NPAD);
    dim3 gg(2, mrows);
    k_hmma<<<gg, 512, SMEM_MMA>>>(bl, br, att, N);

    // ---- join ----
    cudaStreamWaitEvent(0, evJoin, 0);

    // dst-centric aggregation + epilogue + BN stats
    k_agg<<<(N + 7) / 8, 256>>>(att, bias, du, N);

    // BN normalize
    k_bnnorm<<<512, 256>>>(gamma, beta, (float*)d_out, N);
}

// round 11
// speedup vs baseline: 1.0529x; 1.0529x over previous
#include <cuda_runtime.h>
#include <cuda_bf16.h>
#include <cstdint>

#define NMAXP 10240          // padded row capacity (N=10000 -> 79*128=10112)
#define D 256
#define EMAX 200000

// ---------------- scratch (no allocation allowed) ----------------
__device__ float g_xl[NMAXP * D];
__device__ float g_xr[NMAXP * D];
__device__ float g_agg[NMAXP * D];
__device__ float g_ql[NMAXP];            // att . xl[i]
__device__ __align__(16) float g_colsum[D];
__device__ __align__(16) float g_colsumsq[D];
__device__ int   g_is32;
__device__ int   g_total;
// CSR by destination (unordered base allocation)
__device__ int g_deg[NMAXP];
__device__ int g_off[NMAXP];
__device__ int g_cur[NMAXP];
__device__ int g_csr_src[EMAX];
// bf16 split operands
__device__ __nv_bfloat16 g_ah[NMAXP * D];
__device__ __nv_bfloat16 g_al[NMAXP * D];
__device__ __nv_bfloat16 g_bh[512 * D];   // B[n][k] = W[k][n], n in [0,512)
__device__ __nv_bfloat16 g_bl[512 * D];

// ================= helpers =========================================
__device__ __forceinline__ uint32_t smem_u32(const void* p) {
    uint32_t a;
    asm("{ .reg .u64 t; cvta.to.shared.u64 t, %1; cvt.u32.u64 %0, t; }" : "=r"(a) : "l"(p));
    return a;
}
__device__ __forceinline__ void ldsm_x4(uint32_t& r0, uint32_t& r1, uint32_t& r2,
                                        uint32_t& r3, uint32_t a) {
    asm volatile("ldmatrix.sync.aligned.m8n8.x4.shared.b16 {%0,%1,%2,%3}, [%4];"
                 : "=r"(r0), "=r"(r1), "=r"(r2), "=r"(r3) : "r"(a));
}
__device__ __forceinline__ void mma_bf16(float* d, const uint32_t* a, const uint32_t* b) {
    asm volatile(
        "mma.sync.aligned.m16n8k16.row.col.f32.bf16.bf16.f32 "
        "{%0,%1,%2,%3},{%4,%5,%6,%7},{%8,%9},{%0,%1,%2,%3};"
        : "+f"(d[0]), "+f"(d[1]), "+f"(d[2]), "+f"(d[3])
        : "r"(a[0]), "r"(a[1]), "r"(a[2]), "r"(a[3]), "r"(b[0]), "r"(b[1]));
}
__device__ __forceinline__ void cpasync16(uint32_t dst, const void* src) {
    asm volatile("{ .reg .u64 g; cvta.to.global.u64 g, %1;"
                 "  cp.async.cg.shared.global [%0], [g], 16; }"
                 :: "r"(dst), "l"(src) : "memory");
}

// ---------------- init: zero counters + detect dtype ----------------
__global__ void k_init(const long long* ei, int E, int N) {
    int tid = blockIdx.x * blockDim.x + threadIdx.x;
    int stride = gridDim.x * blockDim.x;
    for (int i = tid; i < N; i += stride) g_deg[i] = 0;
    if (blockIdx.x == 0) {
        if (threadIdx.x < D) {
            g_colsum[threadIdx.x] = 0.f;
            g_colsumsq[threadIdx.x] = 0.f;
        }
        if (threadIdx.x == 0) g_total = 0;
    }
    if (blockIdx.x == 1) {
        int bad = 0;
        int lim = E < 2048 ? E : 2048;
        for (int i = threadIdx.x; i < lim; i += blockDim.x) {
            long long v = ei[i];
            if (v < 0 || v >= (long long)N) bad = 1;
        }
        int any = __syncthreads_or(bad);
        if (threadIdx.x == 0) g_is32 = any ? 1 : 0;
    }
}

// ---------------- CSR build: count (2 edges/thread) -----------------
__global__ void k_count(const void* __restrict__ ei, int E) {
    int i0 = (blockIdx.x * blockDim.x + threadIdx.x) * 2;
    if (i0 >= E) return;
    int is32 = g_is32;
    int m = min(2, E - i0);
    int d[2];
#pragma unroll
    for (int j = 0; j < 2; j++)
        if (j < m)
            d[j] = is32 ? __ldg((const int*)ei + E + i0 + j)
                        : (int)__ldg((const long long*)ei + E + i0 + j);
#pragma unroll
    for (int j = 0; j < 2; j++)
        if (j < m) atomicAdd(&g_deg[d[j]], 1);
}

// ---------------- CSR build: unordered base allocation ---------------
__global__ void k_alloc(int N) {
    int i = blockIdx.x * blockDim.x + threadIdx.x;
    int lane = threadIdx.x & 31;
    int d = (i < N) ? g_deg[i] : 0;
    int p = d;
#pragma unroll
    for (int o = 1; o < 32; o <<= 1) {
        int t = __shfl_up_sync(0xffffffffu, p, o);
        if (lane >= o) p += t;
    }
    int total = __shfl_sync(0xffffffffu, p, 31);
    int base = 0;
    if (lane == 0) base = atomicAdd(&g_total, total);
    base = __shfl_sync(0xffffffffu, base, 0);
    int off = base + p - d;
    if (i < N) {
        g_off[i] = off;
        g_cur[i] = off;
    }
}

// ---------------- CSR build: fill (2 edges/thread) -------------------
__global__ void k_fill(const void* __restrict__ ei, int E) {
    int i0 = (blockIdx.x * blockDim.x + threadIdx.x) * 2;
    if (i0 >= E) return;
    int is32 = g_is32;
    int m = min(2, E - i0);
    int s[2], d[2], pos[2];
#pragma unroll
    for (int j = 0; j < 2; j++) {
        if (j < m) {
            if (is32) {
                s[j] = __ldg((const int*)ei + i0 + j);
                d[j] = __ldg((const int*)ei + E + i0 + j);
            } else {
                s[j] = (int)__ldg((const long long*)ei + i0 + j);
                d[j] = (int)__ldg((const long long*)ei + E + i0 + j);
            }
        }
    }
#pragma unroll
    for (int j = 0; j < 2; j++)
        if (j < m) pos[j] = atomicAdd(&g_cur[d[j]], 1);
#pragma unroll
    for (int j = 0; j < 2; j++)
        if (j < m) g_csr_src[pos[j]] = s[j];
}

// ---------------- fused conversions: W transpose + x hi/lo split ------
__global__ void k_conv(const float* __restrict__ x, const float* __restrict__ Wl,
                       const float* __restrict__ Wr, int N, int NPAD) {
    if (blockIdx.x < 128) {
        __shared__ __nv_bfloat16 sh[32][33];
        __shared__ __nv_bfloat16 sl[32][33];
        int n0 = (blockIdx.x & 15) * 32;
        int k0 = (blockIdx.x >> 4) * 32;
        int tid = threadIdx.x;
        int c = tid & 31;
        int r = tid >> 5;
#pragma unroll
        for (int i = 0; i < 4; i++) {
            int k = r + i * 8;
            int n = n0 + c;
            float v = (n < 256) ? Wl[(size_t)(k0 + k) * 256 + n]
                                : Wr[(size_t)(k0 + k) * 256 + (n - 256)];
            __nv_bfloat16 h = __float2bfloat16(v);
            sh[k][c] = h;
            sl[k][c] = __float2bfloat16(v - __bfloat162float(h));
        }
        __syncthreads();
        int nn = tid >> 4;
        int kk = (tid & 15) * 2;
#pragma unroll
        for (int i = 0; i < 2; i++) {
            int nl = nn + i * 16;
            int n = n0 + nl;
            *(__nv_bfloat162*)&g_bh[(size_t)n * D + k0 + kk] = __nv_bfloat162(sh[kk][nl], sh[kk + 1][nl]);
            *(__nv_bfloat162*)&g_bl[(size_t)n * D + k0 + kk] = __nv_bfloat162(sl[kk][nl], sl[kk + 1][nl]);
        }
    } else {
        int gid = (blockIdx.x - 128) * 256 + threadIdx.x;
        int total = NPAD * (D / 4);
        if (gid >= total) return;
        int base = gid * 4;
        int r = base >> 8;
        float4 v = (r < N) ? *(const float4*)(x + base) : make_float4(0.f, 0.f, 0.f, 0.f);
        __nv_bfloat16 h0 = __float2bfloat16(v.x), h1 = __float2bfloat16(v.y);
        __nv_bfloat16 h2 = __float2bfloat16(v.z), h3 = __float2bfloat16(v.w);
        __nv_bfloat16 l0 = __float2bfloat16(v.x - __bfloat162float(h0));
        __nv_bfloat16 l1 = __float2bfloat16(v.y - __bfloat162float(h1));
        __nv_bfloat16 l2 = __float2bfloat16(v.z - __bfloat162float(h2));
        __nv_bfloat16 l3 = __float2bfloat16(v.w - __bfloat162float(h3));
        __nv_bfloat162* ph = (__nv_bfloat162*)(g_ah + base);
        __nv_bfloat162* pl = (__nv_bfloat162*)(g_al + base);
        ph[0] = __nv_bfloat162(h0, h1); ph[1] = __nv_bfloat162(h2, h3);
        pl[0] = __nv_bfloat162(l0, l1); pl[1] = __nv_bfloat162(l2, l3);
    }
}

// ---------------- HMMA 3xBF16 fused GEMM (R9 version) -----------------
#define SMSTRIDE 144
#define ASZ (128 * SMSTRIDE)
#define BSZ (256 * SMSTRIDE)
#define STG (2 * ASZ + 2 * BSZ)
#define OFF_AH 0
#define OFF_AL ASZ
#define OFF_BH (2 * ASZ)
#define OFF_BL (2 * ASZ + BSZ)

__global__ void __launch_bounds__(512, 1)
k_hmma(const float* __restrict__ bl, const float* __restrict__ br, int N) {
    extern __shared__ char sm[];
    uint32_t sb = smem_u32(sm);
    const int tid = threadIdx.x, lane = tid & 31, warp = tid >> 5;
    const int wm = warp >> 2, wn = warp & 3;
    const int row0 = blockIdx.y * 128;
    const int ncol0 = blockIdx.x * 256;

    float acc[2][8][4];
#pragma unroll
    for (int mt = 0; mt < 2; mt++)
#pragma unroll
        for (int nt = 0; nt < 8; nt++)
#pragma unroll
            for (int i = 0; i < 4; i++) acc[mt][nt][i] = 0.f;

    auto issue = [&](int c) {
        uint32_t s0 = sb + (c & 1) * STG;
        int kc = c * 64;
#pragma unroll
        for (int i = 0; i < 12; i++) {
            int idx = tid + i * 512;
            int r = idx >> 3, g = idx & 7;
            if (r < 256) {
                int ar = r & 127;
                uint32_t dst = s0 + ((r < 128) ? OFF_AH : OFF_AL)
                             + (uint32_t)(ar * SMSTRIDE + g * 16);
                const __nv_bfloat16* srcb = (r < 128) ? g_ah : g_al;
                cpasync16(dst, srcb + (size_t)(row0 + ar) * D + kc + g * 8);
            } else {
                int br_ = (r - 256) & 255;
                uint32_t dst = s0 + ((r < 512) ? OFF_BH : OFF_BL)
                             + (uint32_t)(br_ * SMSTRIDE + g * 16);
                const __nv_bfloat16* srcb = (r < 512) ? g_bh : g_bl;
                cpasync16(dst, srcb + (size_t)(ncol0 + br_) * D + kc + g * 8);
            }
        }
        asm volatile("cp.async.commit_group;" ::: "memory");
    };

    issue(0);
    for (int c = 0; c < 4; c++) {
        if (c < 3) {
            issue(c + 1);
            asm volatile("cp.async.wait_group 1;" ::: "memory");
        } else {
            asm volatile("cp.async.wait_group 0;" ::: "memory");
        }
        __syncthreads();

        uint32_t s0 = sb + (c & 1) * STG;
        uint32_t aoffB = (uint32_t)((wm * 32 + (lane & 15)) * SMSTRIDE + (lane >> 4) * 16);
        uint32_t nsel = (uint32_t)(lane >> 4);
        uint32_t nloc = (uint32_t)(lane & 7);
        uint32_t khalf = (uint32_t)((lane >> 3) & 1);

#pragma unroll
        for (int kt = 0; kt < 4; kt++) {
            uint32_t kb = kt * 32;
            uint32_t ah[2][4], al[2][4];
#pragma unroll
            for (int mt = 0; mt < 2; mt++) {
                uint32_t adr = s0 + OFF_AH + aoffB + mt * 16 * SMSTRIDE + kb;
                ldsm_x4(ah[mt][0], ah[mt][1], ah[mt][2], ah[mt][3], adr);
                ldsm_x4(al[mt][0], al[mt][1], al[mt][2], al[mt][3], adr + ASZ);
            }
            uint32_t bh[4][4], blo[4][4];
#pragma unroll
            for (int p = 0; p < 4; p++) {
                uint32_t n = (uint32_t)(wn * 64) + (2 * p + nsel) * 8 + nloc;
                uint32_t adr = s0 + OFF_BH + n * SMSTRIDE + kb + khalf * 16;
                ldsm_x4(bh[p][0], bh[p][1], bh[p][2], bh[p][3], adr);
                ldsm_x4(blo[p][0], blo[p][1], blo[p][2], blo[p][3], adr + BSZ);
            }
#pragma unroll
            for (int mt = 0; mt < 2; mt++)
#pragma unroll
                for (int nt = 0; nt < 8; nt++) {
                    const uint32_t* bhp = &bh[nt >> 1][(nt & 1) * 2];
                    const uint32_t* blp = &blo[nt >> 1][(nt & 1) * 2];
                    mma_bf16(acc[mt][nt], ah[mt], bhp);
                    mma_bf16(acc[mt][nt], al[mt], bhp);
                    mma_bf16(acc[mt][nt], ah[mt], blp);
                }
        }
        __syncthreads();
    }

    const float* bsel = (blockIdx.x == 0) ? bl : br;
    float* Cout = (blockIdx.x == 0) ? g_xl : g_xr;
    int colbase = wn * 64;
#pragma unroll
    for (int mt = 0; mt < 2; mt++) {
        int r0 = row0 + wm * 32 + mt * 16 + (lane >> 2);
#pragma unroll
        for (int nt = 0; nt < 8; nt++) {
            int cc = colbase + nt * 8 + (lane & 3) * 2;
            float b0 = bsel[cc], b1 = bsel[cc + 1];
            if (r0 < N) {
                float2 v = make_float2(acc[mt][nt][0] + b0, acc[mt][nt][1] + b1);
                *(float2*)&Cout[(size_t)r0 * D + cc] = v;
            }
            if (r0 + 8 < N) {
                float2 v = make_float2(acc[mt][nt][2] + b0, acc[mt][nt][3] + b1);
                *(float2*)&Cout[(size_t)(r0 + 8) * D + cc] = v;
            }
        }
    }
}

// ---------------- per-node dot: ql[i] = att . xl[i] -------------------
__global__ void __launch_bounds__(256)
k_dots(const float* __restrict__ att, int N) {
    int warp = threadIdx.x >> 5, lane = threadIdx.x & 31;
    int node = blockIdx.x * 8 + warp;
    if (node >= N) return;
    const float4* xl = (const float4*)(g_xl + (size_t)node * D);
    float4 a0 = xl[lane], a1 = xl[lane + 32];
    float4 t0 = ((const float4*)att)[lane];
    float4 t1 = ((const float4*)att)[lane + 32];
    float p = t0.x * a0.x;
    p = fmaf(t0.y, a0.y, p); p = fmaf(t0.z, a0.z, p); p = fmaf(t0.w, a0.w, p);
    p = fmaf(t1.x, a1.x, p); p = fmaf(t1.y, a1.y, p);
    p = fmaf(t1.z, a1.z, p); p = fmaf(t1.w, a1.w, p);
#pragma unroll
    for (int o = 16; o; o >>= 1) p += __shfl_xor_sync(0xffffffffu, p, o);
    if (lane == 0) g_ql[node] = p;
}

// ---------------- dst-centric aggregation + epilogue -----------------
// score = 0.6*(ql[src]+qr[dst]) + 0.4*sum att_d*|xl_d+xr_d|  (exact lrelu(0.2))
// Gather pipelined via per-warp cp.async double buffer (lane-private chunks).
__global__ void __launch_bounds__(256)
k_agg(const float* __restrict__ att, const float* __restrict__ bias,
      const float* __restrict__ du, int N) {
    __shared__ float s_sum[D];
    __shared__ float s_sq[D];
    __shared__ __align__(16) float4 pbuf[8][2][128];   // [warp][stage][row0|row1]
    int tid = threadIdx.x, warp = tid >> 5, lane = tid & 31;
    for (int i = tid; i < D; i += 256) { s_sum[i] = 0.f; s_sq[i] = 0.f; }
    __syncthreads();

    int dst = blockIdx.x * 8 + warp;
    if (dst < N) {
        uint32_t pb = smem_u32(&pbuf[warp][0][0]) + (uint32_t)lane * 16;

        const float4* xrd = (const float4*)(g_xr + (size_t)dst * D);
        float4 r0 = xrd[lane], r1 = xrd[lane + 32];
        float4 t0 = ((const float4*)att)[lane];
        float4 t1 = ((const float4*)att)[lane + 32];

        // qr[dst] = att . xr[dst]
        float qrd = t0.x * r0.x;
        qrd = fmaf(t0.y, r0.y, qrd); qrd = fmaf(t0.z, r0.z, qrd); qrd = fmaf(t0.w, r0.w, qrd);
        qrd = fmaf(t1.x, r1.x, qrd); qrd = fmaf(t1.y, r1.y, qrd);
        qrd = fmaf(t1.z, r1.z, qrd); qrd = fmaf(t1.w, r1.w, qrd);
#pragma unroll
        for (int o = 16; o; o >>= 1) qrd += __shfl_xor_sync(0xffffffffu, qrd, o);

        float4 acc0 = make_float4(0.f, 0.f, 0.f, 0.f);
        float4 acc1 = make_float4(0.f, 0.f, 0.f, 0.f);
        float den = 0.f;
        bool lo = lane < 16;
        float ql0q[2], ql1q[2];

        int off = g_off[dst];
        int end = g_cur[dst];           // after k_fill, cur == off + deg

        for (int base = off - 1; base < end; base += 32) {
            int nsrc = -1;
            int idx = base + lane;
            if (idx >= off && idx < end) nsrc = g_csr_src[idx];
            else if (idx == off - 1) nsrc = dst;     // self-loop slot
            int m = min(32, end - base);
            int npairs = m >> 1;

            // pipeline prefetch of edge-pairs into smem double buffer
            auto prefetch = [&](int p) {
                int nb = p & 1;
                int s0i = __shfl_sync(0xffffffffu, nsrc, 2 * p);
                int s1i = __shfl_sync(0xffffffffu, nsrc, 2 * p + 1);
                ql0q[nb] = __ldg(g_ql + s0i);
                ql1q[nb] = __ldg(g_ql + s1i);
                const char* q0 = (const char*)(g_xl + (size_t)s0i * D) + lane * 16;
                const char* q1 = (const char*)(g_xl + (size_t)s1i * D) + lane * 16;
                uint32_t dd = pb + (uint32_t)nb * 2048;
                cpasync16(dd,        q0);
                cpasync16(dd + 512,  q0 + 512);
                cpasync16(dd + 1024, q1);
                cpasync16(dd + 1536, q1 + 512);
                asm volatile("cp.async.commit_group;" ::: "memory");
            };

            if (npairs > 0) prefetch(0);
            for (int p = 0; p < npairs; p++) {
                int nb = p & 1;
                if (p + 1 < npairs) {
                    prefetch(p + 1);
                    asm volatile("cp.async.wait_group 1;" ::: "memory");
                } else {
                    asm volatile("cp.async.wait_group 0;" ::: "memory");
                }
                const float4* bufp = &pbuf[warp][nb][0];
                float4 a00 = bufp[lane],      a01 = bufp[lane + 32];
                float4 a10 = bufp[lane + 64], a11 = bufp[lane + 96];
                float p0, p1;
                p0 = t0.x * fabsf(a00.x + r0.x);
                p0 = fmaf(t0.y, fabsf(a00.y + r0.y), p0);
                p0 = fmaf(t0.z, fabsf(a00.z + r0.z), p0);
                p0 = fmaf(t0.w, fabsf(a00.w + r0.w), p0);
                p0 = fmaf(t1.x, fabsf(a01.x + r1.x), p0);
                p0 = fmaf(t1.y, fabsf(a01.y + r1.y), p0);
                p0 = fmaf(t1.z, fabsf(a01.z + r1.z), p0);
                p0 = fmaf(t1.w, fabsf(a01.w + r1.w), p0);
                p1 = t0.x * fabsf(a10.x + r0.x);
                p1 = fmaf(t0.y, fabsf(a10.y + r0.y), p1);
                p1 = fmaf(t0.z, fabsf(a10.z + r0.z), p1);
                p1 = fmaf(t0.w, fabsf(a10.w + r0.w), p1);
                p1 = fmaf(t1.x, fabsf(a11.x + r1.x), p1);
                p1 = fmaf(t1.y, fabsf(a11.y + r1.y), p1);
                p1 = fmaf(t1.z, fabsf(a11.z + r1.z), p1);
                p1 = fmaf(t1.w, fabsf(a11.w + r1.w), p1);
                float c = lo ? p0 : p1;
                float dd = lo ? p1 : p0;
                c += __shfl_xor_sync(0xffffffffu, dd, 16);
                c += __shfl_xor_sync(0xffffffffu, c, 8);
                c += __shfl_xor_sync(0xffffffffu, c, 4);
                c += __shfl_xor_sync(0xffffffffu, c, 2);
                c += __shfl_xor_sync(0xffffffffu, c, 1);
                float qe = lo ? ql0q[nb] : ql1q[nb];
                c = __expf(fmaf(0.4f, c, 0.6f * (qe + qrd)));
                float ev0 = __shfl_sync(0xffffffffu, c, 0);
                float ev1 = __shfl_sync(0xffffffffu, c, 16);
                den += ev0 + ev1;
                acc0.x = fmaf(ev0, a00.x, fmaf(ev1, a10.x, acc0.x));
                acc0.y = fmaf(ev0, a00.y, fmaf(ev1, a10.y, acc0.y));
                acc0.z = fmaf(ev0, a00.z, fmaf(ev1, a10.z, acc0.z));
                acc0.w = fmaf(ev0, a00.w, fmaf(ev1, a10.w, acc0.w));
                acc1.x = fmaf(ev0, a01.x, fmaf(ev1, a11.x, acc1.x));
                acc1.y = fmaf(ev0, a01.y, fmaf(ev1, a11.y, acc1.y));
                acc1.z = fmaf(ev0, a01.z, fmaf(ev1, a11.z, acc1.z));
                acc1.w = fmaf(ev0, a01.w, fmaf(ev1, a11.w, acc1.w));
            }
            if (m & 1) {    // leftover odd edge: direct load
                int e = m - 1;
                int src = __shfl_sync(0xffffffffu, nsrc, e);
                float qls = __ldg(g_ql + src);
                const float4* xls = (const float4*)(g_xl + (size_t)src * D);
                float4 a0 = xls[lane], a1 = xls[lane + 32];
                float p;
                p = t0.x * fabsf(a0.x + r0.x);
                p = fmaf(t0.y, fabsf(a0.y + r0.y), p);
                p = fmaf(t0.z, fabsf(a0.z + r0.z), p);
                p = fmaf(t0.w, fabsf(a0.w + r0.w), p);
                p = fmaf(t1.x, fabsf(a1.x + r1.x), p);
                p = fmaf(t1.y, fabsf(a1.y + r1.y), p);
                p = fmaf(t1.z, fabsf(a1.z + r1.z), p);
                p = fmaf(t1.w, fabsf(a1.w + r1.w), p);
#pragma unroll
                for (int o = 16; o; o >>= 1) p += __shfl_xor_sync(0xffffffffu, p, o);
                float ev = __expf(fmaf(0.4f, p, 0.6f * (qls + qrd)));
                den += ev;
                acc0.x = fmaf(ev, a0.x, acc0.x); acc0.y = fmaf(ev, a0.y, acc0.y);
                acc0.z = fmaf(ev, a0.z, acc0.z); acc0.w = fmaf(ev, a0.w, acc0.w);
                acc1.x = fmaf(ev, a1.x, acc1.x); acc1.y = fmaf(ev, a1.y, acc1.y);
                acc1.z = fmaf(ev, a1.z, acc1.z); acc1.w = fmaf(ev, a1.w, acc1.w);
            }
        }

        float inv = 1.f / den;
        const float4* dup = (const float4*)(du + (size_t)dst * D);
        float4 u0 = dup[lane], u1 = dup[lane + 32];
        const float4* bp = (const float4*)bias;
        float4 b0 = bp[lane], b1 = bp[lane + 32];

        float4 v0, v1;
        v0.x = fmaxf(acc0.x * inv + b0.x, 0.f); v0.x = (u0.x >= 0.5f) ? v0.x * 2.f : 0.f;
        v0.y = fmaxf(acc0.y * inv + b0.y, 0.f); v0.y = (u0.y >= 0.5f) ? v0.y * 2.f : 0.f;
        v0.z = fmaxf(acc0.z * inv + b0.z, 0.f); v0.z = (u0.z >= 0.5f) ? v0.z * 2.f : 0.f;
        v0.w = fmaxf(acc0.w * inv + b0.w, 0.f); v0.w = (u0.w >= 0.5f) ? v0.w * 2.f : 0.f;
        v1.x = fmaxf(acc1.x * inv + b1.x, 0.f); v1.x = (u1.x >= 0.5f) ? v1.x * 2.f : 0.f;
        v1.y = fmaxf(acc1.y * inv + b1.y, 0.f); v1.y = (u1.y >= 0.5f) ? v1.y * 2.f : 0.f;
        v1.z = fmaxf(acc1.z * inv + b1.z, 0.f); v1.z = (u1.z >= 0.5f) ? v1.z * 2.f : 0.f;
        v1.w = fmaxf(acc1.w * inv + b1.w, 0.f); v1.w = (u1.w >= 0.5f) ? v1.w * 2.f : 0.f;

        float4* op = (float4*)(g_agg + (size_t)dst * D);
        op[lane] = v0; op[lane + 32] = v1;

        int c0 = lane * 4, c1 = 128 + lane * 4;
        atomicAdd(&s_sum[c0 + 0], v0.x); atomicAdd(&s_sq[c0 + 0], v0.x * v0.x);
        atomicAdd(&s_sum[c0 + 1], v0.y); atomicAdd(&s_sq[c0 + 1], v0.y * v0.y);
        atomicAdd(&s_sum[c0 + 2], v0.z); atomicAdd(&s_sq[c0 + 2], v0.z * v0.z);
        atomicAdd(&s_sum[c0 + 3], v0.w); atomicAdd(&s_sq[c0 + 3], v0.w * v0.w);
        atomicAdd(&s_sum[c1 + 0], v1.x); atomicAdd(&s_sq[c1 + 0], v1.x * v1.x);
        atomicAdd(&s_sum[c1 + 1], v1.y); atomicAdd(&s_sq[c1 + 1], v1.y * v1.y);
        atomicAdd(&s_sum[c1 + 2], v1.z); atomicAdd(&s_sq[c1 + 2], v1.z * v1.z);
        atomicAdd(&s_sum[c1 + 3], v1.w); atomicAdd(&s_sq[c1 + 3], v1.w * v1.w);
    }
    __syncthreads();
    atomicAdd(&g_colsum[tid], s_sum[tid]);
    atomicAdd(&g_colsumsq[tid], s_sq[tid]);
}

// ---------------- final BN normalize --------------------------------
__global__ void k_bnnorm(const float* __restrict__ gamma, const float* __restrict__ beta,
                         float* __restrict__ out, int N) {
    int d = threadIdx.x;
    float invN = 1.f / (float)N;
    float mean = g_colsum[d] * invN;
    float var = g_colsumsq[d] * invN - mean * mean;
    float inv = rsqrtf(var + 1e-5f);
    float ga = gamma[d], be = beta[d];
    for (int r = blockIdx.x; r < N; r += gridDim.x) {
        out[(size_t)r * D + d] = ga * (g_agg[(size_t)r * D + d] - mean) * inv + be;
    }
}

// ---------------- launch ---------------------------------------------
extern "C" void kernel_launch(void* const* d_in, const int* in_sizes, int n_in,
                              void* d_out, int out_size) {
    (void)n_in; (void)out_size;
    const float* x     = (const float*)d_in[0];
    const void*  ei    = d_in[1];
    const float* Wl    = (const float*)d_in[2];
    const float* bl    = (const float*)d_in[3];
    const float* Wr    = (const float*)d_in[4];
    const float* br    = (const float*)d_in[5];
    const float* att   = (const float*)d_in[6];
    const float* bias  = (const float*)d_in[7];
    const float* gamma = (const float*)d_in[8];
    const float* beta  = (const float*)d_in[9];
    const float* du    = (const float*)d_in[10];

    int N = in_sizes[0] / D;
    int E = in_sizes[1] / 2;
    int mrows = (N + 127) / 128;
    int NPAD = mrows * 128;

    const int SMEM_MMA = 2 * STG;   // 221184 bytes
    static cudaStream_t s2 = nullptr;
    static cudaEvent_t evFork = nullptr, evJoin = nullptr;
    if (!s2) {
        cudaFuncSetAttribute(k_hmma, cudaFuncAttributeMaxDynamicSharedMemorySize, SMEM_MMA);
        cudaStreamCreateWithFlags(&s2, cudaStreamNonBlocking);
        cudaEventCreateWithFlags(&evFork, cudaEventDisableTiming);
        cudaEventCreateWithFlags(&evJoin, cudaEventDisableTiming);
    }

    // ---- fork: CSR chain on s2, conv+GEMM chain on main ----
    cudaEventRecord(evFork, 0);
    cudaStreamWaitEvent(s2, evFork, 0);

    k_init<<<40, 256, 0, s2>>>((const long long*)ei, E, N);
    k_count<<<(E / 2 + 256) / 256, 256, 0, s2>>>(ei, E);
    k_alloc<<<(N + 255) / 256, 256, 0, s2>>>(N);
    k_fill<<<(E / 2 + 256) / 256, 256, 0, s2>>>(ei, E);
    cudaEventRecord(evJoin, s2);

    int xblocks = (NPAD * (D / 4) + 255) / 256;
    k_conv<<<128 + xblocks, 256>>>(x, Wl, Wr, N, NPAD);
    dim3 gg(2, mrows);
    k_hmma<<<gg, 512, SMEM_MMA>>>(bl, br, N);
    k_dots<<<(N + 7) / 8, 256>>>(att, N);

    // ---- join ----
    cudaStreamWaitEvent(0, evJoin, 0);

    // dst-centric aggregation + epilogue + BN stats
    k_agg<<<(N + 7) / 8, 256>>>(att, bias, du, N);

    // BN normalize
    k_bnnorm<<<512, 256>>>(gamma, beta, (float*)d_out, N);
}

// round 12
// speedup vs baseline: 1.0876x; 1.0330x over previous
#include <cuda_runtime.h>
#include <cuda_bf16.h>
#include <cstdint>

#define NMAXP 10240          // padded row capacity (N=10000 -> 79*128=10112)
#define D 256
#define EMAX 200000

// ---------------- scratch (no allocation allowed) ----------------
__device__ float g_xl[NMAXP * D];
__device__ float g_xr[NMAXP * D];
__device__ float g_agg[NMAXP * D];
__device__ float g_ql[NMAXP];            // att . xl[i]
__device__ __align__(16) float g_colsum[D];
__device__ __align__(16) float g_colsumsq[D];
__device__ int   g_is32;
__device__ int   g_total;
// CSR by destination (unordered base allocation)
__device__ int g_deg[NMAXP];
__device__ int g_off[NMAXP];
__device__ int g_cur[NMAXP];
__device__ int g_csr_src[EMAX];
// bf16 split operands
__device__ __nv_bfloat16 g_ah[NMAXP * D];
__device__ __nv_bfloat16 g_al[NMAXP * D];
__device__ __nv_bfloat16 g_bh[512 * D];   // B[n][k] = W[k][n], n in [0,512)
__device__ __nv_bfloat16 g_bl[512 * D];

// ================= helpers =========================================
__device__ __forceinline__ uint32_t smem_u32(const void* p) {
    uint32_t a;
    asm("{ .reg .u64 t; cvta.to.shared.u64 t, %1; cvt.u32.u64 %0, t; }" : "=r"(a) : "l"(p));
    return a;
}
__device__ __forceinline__ void ldsm_x4(uint32_t& r0, uint32_t& r1, uint32_t& r2,
                                        uint32_t& r3, uint32_t a) {
    asm volatile("ldmatrix.sync.aligned.m8n8.x4.shared.b16 {%0,%1,%2,%3}, [%4];"
                 : "=r"(r0), "=r"(r1), "=r"(r2), "=r"(r3) : "r"(a));
}
__device__ __forceinline__ void mma_bf16(float* d, const uint32_t* a, const uint32_t* b) {
    asm volatile(
        "mma.sync.aligned.m16n8k16.row.col.f32.bf16.bf16.f32 "
        "{%0,%1,%2,%3},{%4,%5,%6,%7},{%8,%9},{%0,%1,%2,%3};"
        : "+f"(d[0]), "+f"(d[1]), "+f"(d[2]), "+f"(d[3])
        : "r"(a[0]), "r"(a[1]), "r"(a[2]), "r"(a[3]), "r"(b[0]), "r"(b[1]));
}
__device__ __forceinline__ void cpasync16(uint32_t dst, const void* src) {
    asm volatile("{ .reg .u64 g; cvta.to.global.u64 g, %1;"
                 "  cp.async.cg.shared.global [%0], [g], 16; }"
                 :: "r"(dst), "l"(src) : "memory");
}

// ---------------- init: zero counters + detect dtype ----------------
__global__ void k_init(const long long* ei, int E, int N) {
    int tid = blockIdx.x * blockDim.x + threadIdx.x;
    int stride = gridDim.x * blockDim.x;
    for (int i = tid; i < N; i += stride) g_deg[i] = 0;
    if (blockIdx.x == 0) {
        if (threadIdx.x < D) {
            g_colsum[threadIdx.x] = 0.f;
            g_colsumsq[threadIdx.x] = 0.f;
        }
        if (threadIdx.x == 0) g_total = 0;
    }
    if (blockIdx.x == 1) {
        int bad = 0;
        int lim = E < 2048 ? E : 2048;
        for (int i = threadIdx.x; i < lim; i += blockDim.x) {
            long long v = ei[i];
            if (v < 0 || v >= (long long)N) bad = 1;
        }
        int any = __syncthreads_or(bad);
        if (threadIdx.x == 0) g_is32 = any ? 1 : 0;
    }
}

// ---------------- CSR build: count (2 edges/thread) -----------------
__global__ void k_count(const void* __restrict__ ei, int E) {
    int i0 = (blockIdx.x * blockDim.x + threadIdx.x) * 2;
    if (i0 >= E) return;
    int is32 = g_is32;
    int m = min(2, E - i0);
    int d[2];
#pragma unroll
    for (int j = 0; j < 2; j++)
        if (j < m)
            d[j] = is32 ? __ldg((const int*)ei + E + i0 + j)
                        : (int)__ldg((const long long*)ei + E + i0 + j);
#pragma unroll
    for (int j = 0; j < 2; j++)
        if (j < m) atomicAdd(&g_deg[d[j]], 1);
}

// ---------------- CSR build: unordered base allocation ---------------
__global__ void k_alloc(int N) {
    int i = blockIdx.x * blockDim.x + threadIdx.x;
    int lane = threadIdx.x & 31;
    int d = (i < N) ? g_deg[i] : 0;
    int p = d;
#pragma unroll
    for (int o = 1; o < 32; o <<= 1) {
        int t = __shfl_up_sync(0xffffffffu, p, o);
        if (lane >= o) p += t;
    }
    int total = __shfl_sync(0xffffffffu, p, 31);
    int base = 0;
    if (lane == 0) base = atomicAdd(&g_total, total);
    base = __shfl_sync(0xffffffffu, base, 0);
    int off = base + p - d;
    if (i < N) {
        g_off[i] = off;
        g_cur[i] = off;
    }
}

// ---------------- CSR build: fill (2 edges/thread) -------------------
__global__ void k_fill(const void* __restrict__ ei, int E) {
    int i0 = (blockIdx.x * blockDim.x + threadIdx.x) * 2;
    if (i0 >= E) return;
    int is32 = g_is32;
    int m = min(2, E - i0);
    int s[2], d[2], pos[2];
#pragma unroll
    for (int j = 0; j < 2; j++) {
        if (j < m) {
            if (is32) {
                s[j] = __ldg((const int*)ei + i0 + j);
                d[j] = __ldg((const int*)ei + E + i0 + j);
            } else {
                s[j] = (int)__ldg((const long long*)ei + i0 + j);
                d[j] = (int)__ldg((const long long*)ei + E + i0 + j);
            }
        }
    }
#pragma unroll
    for (int j = 0; j < 2; j++)
        if (j < m) pos[j] = atomicAdd(&g_cur[d[j]], 1);
#pragma unroll
    for (int j = 0; j < 2; j++)
        if (j < m) g_csr_src[pos[j]] = s[j];
}

// ---------------- fused conversions: W transpose + x hi/lo split ------
// Also zeroes g_ql (ordered before k_hmma on the same stream).
__global__ void k_conv(const float* __restrict__ x, const float* __restrict__ Wl,
                       const float* __restrict__ Wr, int N, int NPAD) {
    int zt = blockIdx.x * 256 + threadIdx.x;
    if (zt < NMAXP) g_ql[zt] = 0.f;
    if (blockIdx.x < 128) {
        __shared__ __nv_bfloat16 sh[32][33];
        __shared__ __nv_bfloat16 sl[32][33];
        int n0 = (blockIdx.x & 15) * 32;
        int k0 = (blockIdx.x >> 4) * 32;
        int tid = threadIdx.x;
        int c = tid & 31;
        int r = tid >> 5;
#pragma unroll
        for (int i = 0; i < 4; i++) {
            int k = r + i * 8;
            int n = n0 + c;
            float v = (n < 256) ? Wl[(size_t)(k0 + k) * 256 + n]
                                : Wr[(size_t)(k0 + k) * 256 + (n - 256)];
            __nv_bfloat16 h = __float2bfloat16(v);
            sh[k][c] = h;
            sl[k][c] = __float2bfloat16(v - __bfloat162float(h));
        }
        __syncthreads();
        int nn = tid >> 4;
        int kk = (tid & 15) * 2;
#pragma unroll
        for (int i = 0; i < 2; i++) {
            int nl = nn + i * 16;
            int n = n0 + nl;
            *(__nv_bfloat162*)&g_bh[(size_t)n * D + k0 + kk] = __nv_bfloat162(sh[kk][nl], sh[kk + 1][nl]);
            *(__nv_bfloat162*)&g_bl[(size_t)n * D + k0 + kk] = __nv_bfloat162(sl[kk][nl], sl[kk + 1][nl]);
        }
    } else {
        int gid = (blockIdx.x - 128) * 256 + threadIdx.x;
        int total = NPAD * (D / 4);
        if (gid >= total) return;
        int base = gid * 4;
        int r = base >> 8;
        float4 v = (r < N) ? *(const float4*)(x + base) : make_float4(0.f, 0.f, 0.f, 0.f);
        __nv_bfloat16 h0 = __float2bfloat16(v.x), h1 = __float2bfloat16(v.y);
        __nv_bfloat16 h2 = __float2bfloat16(v.z), h3 = __float2bfloat16(v.w);
        __nv_bfloat16 l0 = __float2bfloat16(v.x - __bfloat162float(h0));
        __nv_bfloat16 l1 = __float2bfloat16(v.y - __bfloat162float(h1));
        __nv_bfloat16 l2 = __float2bfloat16(v.z - __bfloat162float(h2));
        __nv_bfloat16 l3 = __float2bfloat16(v.w - __bfloat162float(h3));
        __nv_bfloat162* ph = (__nv_bfloat162*)(g_ah + base);
        __nv_bfloat162* pl = (__nv_bfloat162*)(g_al + base);
        ph[0] = __nv_bfloat162(h0, h1); ph[1] = __nv_bfloat162(h2, h3);
        pl[0] = __nv_bfloat162(l0, l1); pl[1] = __nv_bfloat162(l2, l3);
    }
}

// ---------------- HMMA 3xBF16 fused GEMM (+ fused ql dot) ------------
#define SMSTRIDE 144
#define ASZ (128 * SMSTRIDE)
#define BSZ (256 * SMSTRIDE)
#define STG (2 * ASZ + 2 * BSZ)
#define OFF_AH 0
#define OFF_AL ASZ
#define OFF_BH (2 * ASZ)
#define OFF_BL (2 * ASZ + BSZ)

__global__ void __launch_bounds__(512, 1)
k_hmma(const float* __restrict__ bl, const float* __restrict__ br,
       const float* __restrict__ att, int N) {
    extern __shared__ char sm[];
    uint32_t sb = smem_u32(sm);
    const int tid = threadIdx.x, lane = tid & 31, warp = tid >> 5;
    const int wm = warp >> 2, wn = warp & 3;
    const int row0 = blockIdx.y * 128;
    const int ncol0 = blockIdx.x * 256;

    float acc[2][8][4];
#pragma unroll
    for (int mt = 0; mt < 2; mt++)
#pragma unroll
        for (int nt = 0; nt < 8; nt++)
#pragma unroll
            for (int i = 0; i < 4; i++) acc[mt][nt][i] = 0.f;

    auto issue = [&](int c) {
        uint32_t s0 = sb + (c & 1) * STG;
        int kc = c * 64;
#pragma unroll
        for (int i = 0; i < 12; i++) {
            int idx = tid + i * 512;
            int r = idx >> 3, g = idx & 7;
            if (r < 256) {
                int ar = r & 127;
                uint32_t dst = s0 + ((r < 128) ? OFF_AH : OFF_AL)
                             + (uint32_t)(ar * SMSTRIDE + g * 16);
                const __nv_bfloat16* srcb = (r < 128) ? g_ah : g_al;
                cpasync16(dst, srcb + (size_t)(row0 + ar) * D + kc + g * 8);
            } else {
                int br_ = (r - 256) & 255;
                uint32_t dst = s0 + ((r < 512) ? OFF_BH : OFF_BL)
                             + (uint32_t)(br_ * SMSTRIDE + g * 16);
                const __nv_bfloat16* srcb = (r < 512) ? g_bh : g_bl;
                cpasync16(dst, srcb + (size_t)(ncol0 + br_) * D + kc + g * 8);
            }
        }
        asm volatile("cp.async.commit_group;" ::: "memory");
    };

    issue(0);
    for (int c = 0; c < 4; c++) {
        if (c < 3) {
            issue(c + 1);
            asm volatile("cp.async.wait_group 1;" ::: "memory");
        } else {
            asm volatile("cp.async.wait_group 0;" ::: "memory");
        }
        __syncthreads();

        uint32_t s0 = sb + (c & 1) * STG;
        uint32_t aoffB = (uint32_t)((wm * 32 + (lane & 15)) * SMSTRIDE + (lane >> 4) * 16);
        uint32_t nsel = (uint32_t)(lane >> 4);
        uint32_t nloc = (uint32_t)(lane & 7);
        uint32_t khalf = (uint32_t)((lane >> 3) & 1);

#pragma unroll
        for (int kt = 0; kt < 4; kt++) {
            uint32_t kb = kt * 32;
            uint32_t ah[2][4], al[2][4];
#pragma unroll
            for (int mt = 0; mt < 2; mt++) {
                uint32_t adr = s0 + OFF_AH + aoffB + mt * 16 * SMSTRIDE + kb;
                ldsm_x4(ah[mt][0], ah[mt][1], ah[mt][2], ah[mt][3], adr);
                ldsm_x4(al[mt][0], al[mt][1], al[mt][2], al[mt][3], adr + ASZ);
            }
            uint32_t bh[4][4], blo[4][4];
#pragma unroll
            for (int p = 0; p < 4; p++) {
                uint32_t n = (uint32_t)(wn * 64) + (2 * p + nsel) * 8 + nloc;
                uint32_t adr = s0 + OFF_BH + n * SMSTRIDE + kb + khalf * 16;
                ldsm_x4(bh[p][0], bh[p][1], bh[p][2], bh[p][3], adr);
                ldsm_x4(blo[p][0], blo[p][1], blo[p][2], blo[p][3], adr + BSZ);
            }
#pragma unroll
            for (int mt = 0; mt < 2; mt++)
#pragma unroll
                for (int nt = 0; nt < 8; nt++) {
                    const uint32_t* bhp = &bh[nt >> 1][(nt & 1) * 2];
                    const uint32_t* blp = &blo[nt >> 1][(nt & 1) * 2];
                    mma_bf16(acc[mt][nt], ah[mt], bhp);
                    mma_bf16(acc[mt][nt], al[mt], bhp);
                    mma_bf16(acc[mt][nt], ah[mt], blp);
                }
        }
        __syncthreads();
    }

    const float* bsel = (blockIdx.x == 0) ? bl : br;
    float* Cout = (blockIdx.x == 0) ? g_xl : g_xr;
    int colbase = wn * 64;
#pragma unroll
    for (int mt = 0; mt < 2; mt++) {
        int r0 = row0 + wm * 32 + mt * 16 + (lane >> 2);
        float d0 = 0.f, d1 = 0.f;      // att-dot partials for rows r0, r0+8
#pragma unroll
        for (int nt = 0; nt < 8; nt++) {
            int cc = colbase + nt * 8 + (lane & 3) * 2;
            float b0 = bsel[cc], b1 = bsel[cc + 1];
            float a0 = att[cc], a1 = att[cc + 1];
            float vx = acc[mt][nt][0] + b0, vy = acc[mt][nt][1] + b1;
            float vz = acc[mt][nt][2] + b0, vw = acc[mt][nt][3] + b1;
            d0 = fmaf(vx, a0, fmaf(vy, a1, d0));
            d1 = fmaf(vz, a0, fmaf(vw, a1, d1));
            if (r0 < N)     *(float2*)&Cout[(size_t)r0 * D + cc]       = make_float2(vx, vy);
            if (r0 + 8 < N) *(float2*)&Cout[(size_t)(r0 + 8) * D + cc] = make_float2(vz, vw);
        }
        if (blockIdx.x == 0) {
            // quad-reduce (lanes sharing the same row differ only in lane&3)
            d0 += __shfl_xor_sync(0xffffffffu, d0, 1);
            d0 += __shfl_xor_sync(0xffffffffu, d0, 2);
            d1 += __shfl_xor_sync(0xffffffffu, d1, 1);
            d1 += __shfl_xor_sync(0xffffffffu, d1, 2);
            if ((lane & 3) == 0) {
                if (r0 < N)     atomicAdd(&g_ql[r0], d0);
                if (r0 + 8 < N) atomicAdd(&g_ql[r0 + 8], d1);
            }
        }
    }
}

// ---------------- dst-centric aggregation + epilogue (R9 exact) ------
// score = 0.6*(ql[src]+qr[dst]) + 0.4*sum att_d*|xl_d+xr_d|  (exact lrelu(0.2))
__global__ void __launch_bounds__(256)
k_agg(const float* __restrict__ att, const float* __restrict__ bias,
      const float* __restrict__ du, int N) {
    __shared__ float s_sum[D];
    __shared__ float s_sq[D];
    int tid = threadIdx.x, warp = tid >> 5, lane = tid & 31;
    for (int i = tid; i < D; i += 256) { s_sum[i] = 0.f; s_sq[i] = 0.f; }
    __syncthreads();

    int dst = blockIdx.x * 8 + warp;
    if (dst < N) {
        const float4* xrd = (const float4*)(g_xr + (size_t)dst * D);
        float4 r0 = xrd[lane], r1 = xrd[lane + 32];
        float4 t0 = ((const float4*)att)[lane];
        float4 t1 = ((const float4*)att)[lane + 32];

        // qr[dst] = att . xr[dst], inline (one butterfly per dst)
        float qrd = t0.x * r0.x;
        qrd = fmaf(t0.y, r0.y, qrd); qrd = fmaf(t0.z, r0.z, qrd); qrd = fmaf(t0.w, r0.w, qrd);
        qrd = fmaf(t1.x, r1.x, qrd); qrd = fmaf(t1.y, r1.y, qrd);
        qrd = fmaf(t1.z, r1.z, qrd); qrd = fmaf(t1.w, r1.w, qrd);
#pragma unroll
        for (int o = 16; o; o >>= 1) qrd += __shfl_xor_sync(0xffffffffu, qrd, o);

        float4 acc0 = make_float4(0.f, 0.f, 0.f, 0.f);
        float4 acc1 = make_float4(0.f, 0.f, 0.f, 0.f);
        float den = 0.f;
        bool lo = lane < 16;

        int off = g_off[dst];
        int end = g_cur[dst];           // after k_fill, cur == off + deg

        for (int base = off - 1; base < end; base += 32) {
            int nsrc = -1;
            int idx = base + lane;
            if (idx >= off && idx < end) nsrc = g_csr_src[idx];
            else if (idx == off - 1) nsrc = dst;     // self-loop slot
            int m = min(32, end - base);
            int e = 0;
            for (; e + 1 < m; e += 2) {
                int s0i = __shfl_sync(0xffffffffu, nsrc, e);
                int s1i = __shfl_sync(0xffffffffu, nsrc, e + 1);
                float ql0 = __ldg(g_ql + s0i);
                float ql1 = __ldg(g_ql + s1i);
                const float4* x0 = (const float4*)(g_xl + (size_t)s0i * D);
                const float4* x1 = (const float4*)(g_xl + (size_t)s1i * D);
                float4 a00 = x0[lane], a01 = x0[lane + 32];
                float4 a10 = x1[lane], a11 = x1[lane + 32];
                float p0, p1;
                p0 = t0.x * fabsf(a00.x + r0.x);
                p0 = fmaf(t0.y, fabsf(a00.y + r0.y), p0);
                p0 = fmaf(t0.z, fabsf(a00.z + r0.z), p0);
                p0 = fmaf(t0.w, fabsf(a00.w + r0.w), p0);
                p0 = fmaf(t1.x, fabsf(a01.x + r1.x), p0);
                p0 = fmaf(t1.y, fabsf(a01.y + r1.y), p0);
                p0 = fmaf(t1.z, fabsf(a01.z + r1.z), p0);
                p0 = fmaf(t1.w, fabsf(a01.w + r1.w), p0);
                p1 = t0.x * fabsf(a10.x + r0.x);
                p1 = fmaf(t0.y, fabsf(a10.y + r0.y), p1);
                p1 = fmaf(t0.z, fabsf(a10.z + r0.z), p1);
                p1 = fmaf(t0.w, fabsf(a10.w + r0.w), p1);
                p1 = fmaf(t1.x, fabsf(a11.x + r1.x), p1);
                p1 = fmaf(t1.y, fabsf(a11.y + r1.y), p1);
                p1 = fmaf(t1.z, fabsf(a11.z + r1.z), p1);
                p1 = fmaf(t1.w, fabsf(a11.w + r1.w), p1);
                float c = lo ? p0 : p1;
                float dd = lo ? p1 : p0;
                c += __shfl_xor_sync(0xffffffffu, dd, 16);
                c += __shfl_xor_sync(0xffffffffu, c, 8);
                c += __shfl_xor_sync(0xffffffffu, c, 4);
                c += __shfl_xor_sync(0xffffffffu, c, 2);
                c += __shfl_xor_sync(0xffffffffu, c, 1);
                float qe = lo ? ql0 : ql1;
                c = __expf(fmaf(0.4f, c, 0.6f * (qe + qrd)));
                float ev0 = __shfl_sync(0xffffffffu, c, 0);
                float ev1 = __shfl_sync(0xffffffffu, c, 16);
                den += ev0 + ev1;
                acc0.x = fmaf(ev0, a00.x, fmaf(ev1, a10.x, acc0.x));
                acc0.y = fmaf(ev0, a00.y, fmaf(ev1, a10.y, acc0.y));
                acc0.z = fmaf(ev0, a00.z, fmaf(ev1, a10.z, acc0.z));
                acc0.w = fmaf(ev0, a00.w, fmaf(ev1, a10.w, acc0.w));
                acc1.x = fmaf(ev0, a01.x, fmaf(ev1, a11.x, acc1.x));
                acc1.y = fmaf(ev0, a01.y, fmaf(ev1, a11.y, acc1.y));
                acc1.z = fmaf(ev0, a01.z, fmaf(ev1, a11.z, acc1.z));
                acc1.w = fmaf(ev0, a01.w, fmaf(ev1, a11.w, acc1.w));
            }
            if (e < m) {
                int src = __shfl_sync(0xffffffffu, nsrc, e);
                float qls = __ldg(g_ql + src);
                const float4* xls = (const float4*)(g_xl + (size_t)src * D);
                float4 a0 = xls[lane], a1 = xls[lane + 32];
                float p;
                p = t0.x * fabsf(a0.x + r0.x);
                p = fmaf(t0.y, fabsf(a0.y + r0.y), p);
                p = fmaf(t0.z, fabsf(a0.z + r0.z), p);
                p = fmaf(t0.w, fabsf(a0.w + r0.w), p);
                p = fmaf(t1.x, fabsf(a1.x + r1.x), p);
                p = fmaf(t1.y, fabsf(a1.y + r1.y), p);
                p = fmaf(t1.z, fabsf(a1.z + r1.z), p);
                p = fmaf(t1.w, fabsf(a1.w + r1.w), p);
#pragma unroll
                for (int o = 16; o; o >>= 1) p += __shfl_xor_sync(0xffffffffu, p, o);
                float ev = __expf(fmaf(0.4f, p, 0.6f * (qls + qrd)));
                den += ev;
                acc0.x = fmaf(ev, a0.x, acc0.x); acc0.y = fmaf(ev, a0.y, acc0.y);
                acc0.z = fmaf(ev, a0.z, acc0.z); acc0.w = fmaf(ev, a0.w, acc0.w);
                acc1.x = fmaf(ev, a1.x, acc1.x); acc1.y = fmaf(ev, a1.y, acc1.y);
                acc1.z = fmaf(ev, a1.z, acc1.z); acc1.w = fmaf(ev, a1.w, acc1.w);
            }
        }

        float inv = 1.f / den;
        const float4* dup = (const float4*)(du + (size_t)dst * D);
        float4 u0 = dup[lane], u1 = dup[lane + 32];
        const float4* bp = (const float4*)bias;
        float4 b0 = bp[lane], b1 = bp[lane + 32];

        float4 v0, v1;
        v0.x = fmaxf(acc0.x * inv + b0.x, 0.f); v0.x = (u0.x >= 0.5f) ? v0.x * 2.f : 0.f;
        v0.y = fmaxf(acc0.y * inv + b0.y, 0.f); v0.y = (u0.y >= 0.5f) ? v0.y * 2.f : 0.f;
        v0.z = fmaxf(acc0.z * inv + b0.z, 0.f); v0.z = (u0.z >= 0.5f) ? v0.z * 2.f : 0.f;
        v0.w = fmaxf(acc0.w * inv + b0.w, 0.f); v0.w = (u0.w >= 0.5f) ? v0.w * 2.f : 0.f;
        v1.x = fmaxf(acc1.x * inv + b1.x, 0.f); v1.x = (u1.x >= 0.5f) ? v1.x * 2.f : 0.f;
        v1.y = fmaxf(acc1.y * inv + b1.y, 0.f); v1.y = (u1.y >= 0.5f) ? v1.y * 2.f : 0.f;
        v1.z = fmaxf(acc1.z * inv + b1.z, 0.f); v1.z = (u1.z >= 0.5f) ? v1.z * 2.f : 0.f;
        v1.w = fmaxf(acc1.w * inv + b1.w, 0.f); v1.w = (u1.w >= 0.5f) ? v1.w * 2.f : 0.f;

        float4* op = (float4*)(g_agg + (size_t)dst * D);
        op[lane] = v0; op[lane + 32] = v1;

        int c0 = lane * 4, c1 = 128 + lane * 4;
        atomicAdd(&s_sum[c0 + 0], v0.x); atomicAdd(&s_sq[c0 + 0], v0.x * v0.x);
        atomicAdd(&s_sum[c0 + 1], v0.y); atomicAdd(&s_sq[c0 + 1], v0.y * v0.y);
        atomicAdd(&s_sum[c0 + 2], v0.z); atomicAdd(&s_sq[c0 + 2], v0.z * v0.z);
        atomicAdd(&s_sum[c0 + 3], v0.w); atomicAdd(&s_sq[c0 + 3], v0.w * v0.w);
        atomicAdd(&s_sum[c1 + 0], v1.x); atomicAdd(&s_sq[c1 + 0], v1.x * v1.x);
        atomicAdd(&s_sum[c1 + 1], v1.y); atomicAdd(&s_sq[c1 + 1], v1.y * v1.y);
        atomicAdd(&s_sum[c1 + 2], v1.z); atomicAdd(&s_sq[c1 + 2], v1.z * v1.z);
        atomicAdd(&s_sum[c1 + 3], v1.w); atomicAdd(&s_sq[c1 + 3], v1.w * v1.w);
    }
    __syncthreads();
    atomicAdd(&g_colsum[tid], s_sum[tid]);
    atomicAdd(&g_colsumsq[tid], s_sq[tid]);
}

// ---------------- final BN normalize --------------------------------
__global__ void k_bnnorm(const float* __restrict__ gamma, const float* __restrict__ beta,
                         float* __restrict__ out, int N) {
    int d = threadIdx.x;
    float invN = 1.f / (float)N;
    float mean = g_colsum[d] * invN;
    float var = g_colsumsq[d] * invN - mean * mean;
    float inv = rsqrtf(var + 1e-5f);
    float ga = gamma[d], be = beta[d];
    for (int r = blockIdx.x; r < N; r += gridDim.x) {
        out[(size_t)r * D + d] = ga * (g_agg[(size_t)r * D + d] - mean) * inv + be;
    }
}

// ---------------- launch ---------------------------------------------
extern "C" void kernel_launch(void* const* d_in, const int* in_sizes, int n_in,
                              void* d_out, int out_size) {
    (void)n_in; (void)out_size;
    const float* x     = (const float*)d_in[0];
    const void*  ei    = d_in[1];
    const float* Wl    = (const float*)d_in[2];
    const float* bl    = (const float*)d_in[3];
    const float* Wr    = (const float*)d_in[4];
    const float* br    = (const float*)d_in[5];
    const float* att   = (const float*)d_in[6];
    const float* bias  = (const float*)d_in[7];
    const float* gamma = (const float*)d_in[8];
    const float* beta  = (const float*)d_in[9];
    const float* du    = (const float*)d_in[10];

    int N = in_sizes[0] / D;
    int E = in_sizes[1] / 2;
    int mrows = (N + 127) / 128;
    int NPAD = mrows * 128;

    const int SMEM_MMA = 2 * STG;   // 221184 bytes
    static cudaStream_t s2 = nullptr;
    static cudaEvent_t evFork = nullptr, evJoin = nullptr;
    if (!s2) {
        cudaFuncSetAttribute(k_hmma, cudaFuncAttributeMaxDynamicSharedMemorySize, SMEM_MMA);
        cudaStreamCreateWithFlags(&s2, cudaStreamNonBlocking);
        cudaEventCreateWithFlags(&evFork, cudaEventDisableTiming);
        cudaEventCreateWithFlags(&evJoin, cudaEventDisableTiming);
    }

    // ---- fork: CSR chain on s2, conv+GEMM chain on main ----
    cudaEventRecord(evFork, 0);
    cudaStreamWaitEvent(s2, evFork, 0);

    k_init<<<40, 256, 0, s2>>>((const long long*)ei, E, N);
    k_count<<<(E / 2 + 256) / 256, 256, 0, s2>>>(ei, E);
    k_alloc<<<(N + 255) / 256, 256, 0, s2>>>(N);
    k_fill<<<(E / 2 + 256) / 256, 256, 0, s2>>>(ei, E);
    cudaEventRecord(evJoin, s2);

    int xblocks = (NPAD * (D / 4) + 255) / 256;
    k_conv<<<128 + xblocks, 256>>>(x, Wl, Wr, N, NPAD);
    dim3 gg(2, mrows);
    k_hmma<<<gg, 512, SMEM_MMA>>>(bl, br, att, N);

    // ---- join ----
    cudaStreamWaitEvent(0, evJoin, 0);

    // dst-centric aggregation + epilogue + BN stats
    k_agg<<<(N + 7) / 8, 256>>>(att, bias, du, N);

    // BN normalize
    k_bnnorm<<<512, 256>>>(gamma, beta, (float*)d_out, N);
}

// round 13
// speedup vs baseline: 1.0954x; 1.0071x over previous
#include <cuda_runtime.h>
#include <cuda_bf16.h>
#include <cstdint>

#define NMAXP 10240          // padded row capacity (N=10000 -> 79*128=10112)
#define D 256
#define EMAX 200000

// ---------------- scratch (no allocation allowed) ----------------
__device__ float g_xl[NMAXP * D];
__device__ float g_xr[NMAXP * D];
__device__ float g_agg[NMAXP * D];
__device__ float g_ql[NMAXP];            // att . xl[i]
__device__ __align__(16) float g_colsum[D];
__device__ __align__(16) float g_colsumsq[D];
__device__ int   g_is32;
__device__ int   g_total;
// CSR by destination (unordered base allocation)
__device__ int g_deg[NMAXP];
__device__ int g_off[NMAXP];
__device__ int g_cur[NMAXP];
__device__ int g_csr_src[EMAX];
// bf16 split operands
__device__ __nv_bfloat16 g_ah[NMAXP * D];
__device__ __nv_bfloat16 g_al[NMAXP * D];
__device__ __nv_bfloat16 g_bh[512 * D];   // B[n][k] = W[k][n], n in [0,512)
__device__ __nv_bfloat16 g_bl[512 * D];

// ================= helpers =========================================
__device__ __forceinline__ uint32_t smem_u32(const void* p) {
    uint32_t a;
    asm("{ .reg .u64 t; cvta.to.shared.u64 t, %1; cvt.u32.u64 %0, t; }" : "=r"(a) : "l"(p));
    return a;
}
__device__ __forceinline__ void ldsm_x4(uint32_t& r0, uint32_t& r1, uint32_t& r2,
                                        uint32_t& r3, uint32_t a) {
    asm volatile("ldmatrix.sync.aligned.m8n8.x4.shared.b16 {%0,%1,%2,%3}, [%4];"
                 : "=r"(r0), "=r"(r1), "=r"(r2), "=r"(r3) : "r"(a));
}
__device__ __forceinline__ void mma_bf16(float* d, const uint32_t* a, const uint32_t* b) {
    asm volatile(
        "mma.sync.aligned.m16n8k16.row.col.f32.bf16.bf16.f32 "
        "{%0,%1,%2,%3},{%4,%5,%6,%7},{%8,%9},{%0,%1,%2,%3};"
        : "+f"(d[0]), "+f"(d[1]), "+f"(d[2]), "+f"(d[3])
        : "r"(a[0]), "r"(a[1]), "r"(a[2]), "r"(a[3]), "r"(b[0]), "r"(b[1]));
}
__device__ __forceinline__ void cpasync16(uint32_t dst, const void* src) {
    asm volatile("{ .reg .u64 g; cvta.to.global.u64 g, %1;"
                 "  cp.async.cg.shared.global [%0], [g], 16; }"
                 :: "r"(dst), "l"(src) : "memory");
}

// ---------------- init: zero counters + detect dtype ----------------
__global__ void k_init(const long long* ei, int E, int N) {
    int tid = blockIdx.x * blockDim.x + threadIdx.x;
    int stride = gridDim.x * blockDim.x;
    for (int i = tid; i < N; i += stride) g_deg[i] = 0;
    if (blockIdx.x == 0) {
        if (threadIdx.x < D) {
            g_colsum[threadIdx.x] = 0.f;
            g_colsumsq[threadIdx.x] = 0.f;
        }
        if (threadIdx.x == 0) g_total = 0;
    }
    if (blockIdx.x == 1) {
        int bad = 0;
        int lim = E < 2048 ? E : 2048;
        for (int i = threadIdx.x; i < lim; i += blockDim.x) {
            long long v = ei[i];
            if (v < 0 || v >= (long long)N) bad = 1;
        }
        int any = __syncthreads_or(bad);
        if (threadIdx.x == 0) g_is32 = any ? 1 : 0;
    }
}

// ---------------- CSR build: count (2 edges/thread) -----------------
__global__ void k_count(const void* __restrict__ ei, int E) {
    int i0 = (blockIdx.x * blockDim.x + threadIdx.x) * 2;
    if (i0 >= E) return;
    int is32 = g_is32;
    int m = min(2, E - i0);
    int d[2];
#pragma unroll
    for (int j = 0; j < 2; j++)
        if (j < m)
            d[j] = is32 ? __ldg((const int*)ei + E + i0 + j)
                        : (int)__ldg((const long long*)ei + E + i0 + j);
#pragma unroll
    for (int j = 0; j < 2; j++)
        if (j < m) atomicAdd(&g_deg[d[j]], 1);
}

// ---------------- CSR build: unordered base allocation ---------------
__global__ void k_alloc(int N) {
    int i = blockIdx.x * blockDim.x + threadIdx.x;
    int lane = threadIdx.x & 31;
    int d = (i < N) ? g_deg[i] : 0;
    int p = d;
#pragma unroll
    for (int o = 1; o < 32; o <<= 1) {
        int t = __shfl_up_sync(0xffffffffu, p, o);
        if (lane >= o) p += t;
    }
    int total = __shfl_sync(0xffffffffu, p, 31);
    int base = 0;
    if (lane == 0) base = atomicAdd(&g_total, total);
    base = __shfl_sync(0xffffffffu, base, 0);
    int off = base + p - d;
    if (i < N) {
        g_off[i] = off;
        g_cur[i] = off;
    }
}

// ---------------- CSR build: fill (2 edges/thread) -------------------
__global__ void k_fill(const void* __restrict__ ei, int E) {
    int i0 = (blockIdx.x * blockDim.x + threadIdx.x) * 2;
    if (i0 >= E) return;
    int is32 = g_is32;
    int m = min(2, E - i0);
    int s[2], d[2], pos[2];
#pragma unroll
    for (int j = 0; j < 2; j++) {
        if (j < m) {
            if (is32) {
                s[j] = __ldg((const int*)ei + i0 + j);
                d[j] = __ldg((const int*)ei + E + i0 + j);
            } else {
                s[j] = (int)__ldg((const long long*)ei + i0 + j);
                d[j] = (int)__ldg((const long long*)ei + E + i0 + j);
            }
        }
    }
#pragma unroll
    for (int j = 0; j < 2; j++)
        if (j < m) pos[j] = atomicAdd(&g_cur[d[j]], 1);
#pragma unroll
    for (int j = 0; j < 2; j++)
        if (j < m) g_csr_src[pos[j]] = s[j];
}

// ---------------- fused conversions: W transpose + x hi/lo split ------
// Also zeroes g_ql (ordered before k_hmma on the same stream).
__global__ void k_conv(const float* __restrict__ x, const float* __restrict__ Wl,
                       const float* __restrict__ Wr, int N, int NPAD) {
    int zt = blockIdx.x * 256 + threadIdx.x;
    if (zt < NMAXP) g_ql[zt] = 0.f;
    if (blockIdx.x < 128) {
        __shared__ __nv_bfloat16 sh[32][33];
        __shared__ __nv_bfloat16 sl[32][33];
        int n0 = (blockIdx.x & 15) * 32;
        int k0 = (blockIdx.x >> 4) * 32;
        int tid = threadIdx.x;
        int c = tid & 31;
        int r = tid >> 5;
#pragma unroll
        for (int i = 0; i < 4; i++) {
            int k = r + i * 8;
            int n = n0 + c;
            float v = (n < 256) ? Wl[(size_t)(k0 + k) * 256 + n]
                                : Wr[(size_t)(k0 + k) * 256 + (n - 256)];
            __nv_bfloat16 h = __float2bfloat16(v);
            sh[k][c] = h;
            sl[k][c] = __float2bfloat16(v - __bfloat162float(h));
        }
        __syncthreads();
        int nn = tid >> 4;
        int kk = (tid & 15) * 2;
#pragma unroll
        for (int i = 0; i < 2; i++) {
            int nl = nn + i * 16;
            int n = n0 + nl;
            *(__nv_bfloat162*)&g_bh[(size_t)n * D + k0 + kk] = __nv_bfloat162(sh[kk][nl], sh[kk + 1][nl]);
            *(__nv_bfloat162*)&g_bl[(size_t)n * D + k0 + kk] = __nv_bfloat162(sl[kk][nl], sl[kk + 1][nl]);
        }
    } else {
        int gid = (blockIdx.x - 128) * 256 + threadIdx.x;
        int total = NPAD * (D / 4);
        if (gid >= total) return;
        int base = gid * 4;
        int r = base >> 8;
        float4 v = (r < N) ? *(const float4*)(x + base) : make_float4(0.f, 0.f, 0.f, 0.f);
        __nv_bfloat16 h0 = __float2bfloat16(v.x), h1 = __float2bfloat16(v.y);
        __nv_bfloat16 h2 = __float2bfloat16(v.z), h3 = __float2bfloat16(v.w);
        __nv_bfloat16 l0 = __float2bfloat16(v.x - __bfloat162float(h0));
        __nv_bfloat16 l1 = __float2bfloat16(v.y - __bfloat162float(h1));
        __nv_bfloat16 l2 = __float2bfloat16(v.z - __bfloat162float(h2));
        __nv_bfloat16 l3 = __float2bfloat16(v.w - __bfloat162float(h3));
        __nv_bfloat162* ph = (__nv_bfloat162*)(g_ah + base);
        __nv_bfloat162* pl = (__nv_bfloat162*)(g_al + base);
        ph[0] = __nv_bfloat162(h0, h1); ph[1] = __nv_bfloat162(h2, h3);
        pl[0] = __nv_bfloat162(l0, l1); pl[1] = __nv_bfloat162(l2, l3);
    }
}

// ---------------- HMMA 3xBF16 fused GEMM (+ fused ql dot) ------------
// Inner loop restructured: B fragments loaded per n-pair to cut peak
// register pressure below the 128-reg/thread ceiling (512 thr/CTA).
#define SMSTRIDE 144
#define ASZ (128 * SMSTRIDE)
#define BSZ (256 * SMSTRIDE)
#define STG (2 * ASZ + 2 * BSZ)
#define OFF_AH 0
#define OFF_AL ASZ
#define OFF_BH (2 * ASZ)
#define OFF_BL (2 * ASZ + BSZ)

__global__ void __launch_bounds__(512, 1)
k_hmma(const float* __restrict__ bl, const float* __restrict__ br,
       const float* __restrict__ att, int N) {
    extern __shared__ char sm[];
    uint32_t sb = smem_u32(sm);
    const int tid = threadIdx.x, lane = tid & 31, warp = tid >> 5;
    const int wm = warp >> 2, wn = warp & 3;
    const int row0 = blockIdx.y * 128;
    const int ncol0 = blockIdx.x * 256;

    float acc[2][8][4];
#pragma unroll
    for (int mt = 0; mt < 2; mt++)
#pragma unroll
        for (int nt = 0; nt < 8; nt++)
#pragma unroll
            for (int i = 0; i < 4; i++) acc[mt][nt][i] = 0.f;

    auto issue = [&](int c) {
        uint32_t s0 = sb + (c & 1) * STG;
        int kc = c * 64;
#pragma unroll
        for (int i = 0; i < 12; i++) {
            int idx = tid + i * 512;
            int r = idx >> 3, g = idx & 7;
            if (r < 256) {
                int ar = r & 127;
                uint32_t dst = s0 + ((r < 128) ? OFF_AH : OFF_AL)
                             + (uint32_t)(ar * SMSTRIDE + g * 16);
                const __nv_bfloat16* srcb = (r < 128) ? g_ah : g_al;
                cpasync16(dst, srcb + (size_t)(row0 + ar) * D + kc + g * 8);
            } else {
                int br_ = (r - 256) & 255;
                uint32_t dst = s0 + ((r < 512) ? OFF_BH : OFF_BL)
                             + (uint32_t)(br_ * SMSTRIDE + g * 16);
                const __nv_bfloat16* srcb = (r < 512) ? g_bh : g_bl;
                cpasync16(dst, srcb + (size_t)(ncol0 + br_) * D + kc + g * 8);
            }
        }
        asm volatile("cp.async.commit_group;" ::: "memory");
    };

    issue(0);
    for (int c = 0; c < 4; c++) {
        if (c < 3) {
            issue(c + 1);
            asm volatile("cp.async.wait_group 1;" ::: "memory");
        } else {
            asm volatile("cp.async.wait_group 0;" ::: "memory");
        }
        __syncthreads();

        uint32_t s0 = sb + (c & 1) * STG;
        uint32_t aoffB = (uint32_t)((wm * 32 + (lane & 15)) * SMSTRIDE + (lane >> 4) * 16);
        uint32_t nsel = (uint32_t)(lane >> 4);
        uint32_t nloc = (uint32_t)(lane & 7);
        uint32_t khalf = (uint32_t)((lane >> 3) & 1);

#pragma unroll
        for (int kt = 0; kt < 4; kt++) {
            uint32_t kb = kt * 32;
            uint32_t ah[2][4], al[2][4];
#pragma unroll
            for (int mt = 0; mt < 2; mt++) {
                uint32_t adr = s0 + OFF_AH + aoffB + mt * 16 * SMSTRIDE + kb;
                ldsm_x4(ah[mt][0], ah[mt][1], ah[mt][2], ah[mt][3], adr);
                ldsm_x4(al[mt][0], al[mt][1], al[mt][2], al[mt][3], adr + ASZ);
            }
            // B fragments loaded per n-pair and consumed immediately
#pragma unroll
            for (int p = 0; p < 4; p++) {
                uint32_t bhf[4], blf[4];
                uint32_t n = (uint32_t)(wn * 64) + (2 * p + nsel) * 8 + nloc;
                uint32_t adr = s0 + OFF_BH + n * SMSTRIDE + kb + khalf * 16;
                ldsm_x4(bhf[0], bhf[1], bhf[2], bhf[3], adr);
                ldsm_x4(blf[0], blf[1], blf[2], blf[3], adr + BSZ);
#pragma unroll
                for (int mt = 0; mt < 2; mt++)
#pragma unroll
                    for (int q = 0; q < 2; q++) {
                        int nt = p * 2 + q;
                        mma_bf16(acc[mt][nt], ah[mt], &bhf[q * 2]);
                        mma_bf16(acc[mt][nt], al[mt], &bhf[q * 2]);
                        mma_bf16(acc[mt][nt], ah[mt], &blf[q * 2]);
                    }
            }
        }
        __syncthreads();
    }

    const float* bsel = (blockIdx.x == 0) ? bl : br;
    float* Cout = (blockIdx.x == 0) ? g_xl : g_xr;
    int colbase = wn * 64;
#pragma unroll
    for (int mt = 0; mt < 2; mt++) {
        int r0 = row0 + wm * 32 + mt * 16 + (lane >> 2);
        float d0 = 0.f, d1 = 0.f;      // att-dot partials for rows r0, r0+8
#pragma unroll
        for (int nt = 0; nt < 8; nt++) {
            int cc = colbase + nt * 8 + (lane & 3) * 2;
            float b0 = bsel[cc], b1 = bsel[cc + 1];
            float a0 = att[cc], a1 = att[cc + 1];
            float vx = acc[mt][nt][0] + b0, vy = acc[mt][nt][1] + b1;
            float vz = acc[mt][nt][2] + b0, vw = acc[mt][nt][3] + b1;
            d0 = fmaf(vx, a0, fmaf(vy, a1, d0));
            d1 = fmaf(vz, a0, fmaf(vw, a1, d1));
            if (r0 < N)     *(float2*)&Cout[(size_t)r0 * D + cc]       = make_float2(vx, vy);
            if (r0 + 8 < N) *(float2*)&Cout[(size_t)(r0 + 8) * D + cc] = make_float2(vz, vw);
        }
        if (blockIdx.x == 0) {
            d0 += __shfl_xor_sync(0xffffffffu, d0, 1);
            d0 += __shfl_xor_sync(0xffffffffu, d0, 2);
            d1 += __shfl_xor_sync(0xffffffffu, d1, 1);
            d1 += __shfl_xor_sync(0xffffffffu, d1, 2);
            if ((lane & 3) == 0) {
                if (r0 < N)     atomicAdd(&g_ql[r0], d0);
                if (r0 + 8 < N) atomicAdd(&g_ql[r0 + 8], d1);
            }
        }
    }
}

// ---------------- dst-centric aggregation + epilogue (R9 exact) ------
// score = 0.6*(ql[src]+qr[dst]) + 0.4*sum att_d*|xl_d+xr_d|  (exact lrelu(0.2))
__global__ void __launch_bounds__(256)
k_agg(const float* __restrict__ att, const float* __restrict__ bias,
      const float* __restrict__ du, int N) {
    __shared__ float s_sum[D];
    __shared__ float s_sq[D];
    int tid = threadIdx.x, warp = tid >> 5, lane = tid & 31;
    for (int i = tid; i < D; i += 256) { s_sum[i] = 0.f; s_sq[i] = 0.f; }
    __syncthreads();

    int dst = blockIdx.x * 8 + warp;
    if (dst < N) {
        const float4* xrd = (const float4*)(g_xr + (size_t)dst * D);
        float4 r0 = xrd[lane], r1 = xrd[lane + 32];
        float4 t0 = ((const float4*)att)[lane];
        float4 t1 = ((const float4*)att)[lane + 32];

        float qrd = t0.x * r0.x;
        qrd = fmaf(t0.y, r0.y, qrd); qrd = fmaf(t0.z, r0.z, qrd); qrd = fmaf(t0.w, r0.w, qrd);
        qrd = fmaf(t1.x, r1.x, qrd); qrd = fmaf(t1.y, r1.y, qrd);
        qrd = fmaf(t1.z, r1.z, qrd); qrd = fmaf(t1.w, r1.w, qrd);
#pragma unroll
        for (int o = 16; o; o >>= 1) qrd += __shfl_xor_sync(0xffffffffu, qrd, o);

        float4 acc0 = make_float4(0.f, 0.f, 0.f, 0.f);
        float4 acc1 = make_float4(0.f, 0.f, 0.f, 0.f);
        float den = 0.f;
        bool lo = lane < 16;

        int off = g_off[dst];
        int end = g_cur[dst];           // after k_fill, cur == off + deg

        for (int base = off - 1; base < end; base += 32) {
            int nsrc = -1;
            int idx = base + lane;
            if (idx >= off && idx < end) nsrc = g_csr_src[idx];
            else if (idx == off - 1) nsrc = dst;     // self-loop slot
            int m = min(32, end - base);
            int e = 0;
            for (; e + 1 < m; e += 2) {
                int s0i = __shfl_sync(0xffffffffu, nsrc, e);
                int s1i = __shfl_sync(0xffffffffu, nsrc, e + 1);
                float ql0 = __ldg(g_ql + s0i);
                float ql1 = __ldg(g_ql + s1i);
                const float4* x0 = (const float4*)(g_xl + (size_t)s0i * D);
                const float4* x1 = (const float4*)(g_xl + (size_t)s1i * D);
                float4 a00 = x0[lane], a01 = x0[lane + 32];
                float4 a10 = x1[lane], a11 = x1[lane + 32];
                float p0, p1;
                p0 = t0.x * fabsf(a00.x + r0.x);
                p0 = fmaf(t0.y, fabsf(a00.y + r0.y), p0);
                p0 = fmaf(t0.z, fabsf(a00.z + r0.z), p0);
                p0 = fmaf(t0.w, fabsf(a00.w + r0.w), p0);
                p0 = fmaf(t1.x, fabsf(a01.x + r1.x), p0);
                p0 = fmaf(t1.y, fabsf(a01.y + r1.y), p0);
                p0 = fmaf(t1.z, fabsf(a01.z + r1.z), p0);
                p0 = fmaf(t1.w, fabsf(a01.w + r1.w), p0);
                p1 = t0.x * fabsf(a10.x + r0.x);
                p1 = fmaf(t0.y, fabsf(a10.y + r0.y), p1);
                p1 = fmaf(t0.z, fabsf(a10.z + r0.z), p1);
                p1 = fmaf(t0.w, fabsf(a10.w + r0.w), p1);
                p1 = fmaf(t1.x, fabsf(a11.x + r1.x), p1);
                p1 = fmaf(t1.y, fabsf(a11.y + r1.y), p1);
                p1 = fmaf(t1.z, fabsf(a11.z + r1.z), p1);
                p1 = fmaf(t1.w, fabsf(a11.w + r1.w), p1);
                float c = lo ? p0 : p1;
                float dd = lo ? p1 : p0;
                c += __shfl_xor_sync(0xffffffffu, dd, 16);
                c += __shfl_xor_sync(0xffffffffu, c, 8);
                c += __shfl_xor_sync(0xffffffffu, c, 4);
                c += __shfl_xor_sync(0xffffffffu, c, 2);
                c += __shfl_xor_sync(0xffffffffu, c, 1);
                float qe = lo ? ql0 : ql1;
                c = __expf(fmaf(0.4f, c, 0.6f * (qe + qrd)));
                float ev0 = __shfl_sync(0xffffffffu, c, 0);
                float ev1 = __shfl_sync(0xffffffffu, c, 16);
                den += ev0 + ev1;
                acc0.x = fmaf(ev0, a00.x, fmaf(ev1, a10.x, acc0.x));
                acc0.y = fmaf(ev0, a00.y, fmaf(ev1, a10.y, acc0.y));
                acc0.z = fmaf(ev0, a00.z, fmaf(ev1, a10.z, acc0.z));
                acc0.w = fmaf(ev0, a00.w, fmaf(ev1, a10.w, acc0.w));
                acc1.x = fmaf(ev0, a01.x, fmaf(ev1, a11.x, acc1.x));
                acc1.y = fmaf(ev0, a01.y, fmaf(ev1, a11.y, acc1.y));
                acc1.z = fmaf(ev0, a01.z, fmaf(ev1, a11.z, acc1.z));
                acc1.w = fmaf(ev0, a01.w, fmaf(ev1, a11.w, acc1.w));
            }
            if (e < m) {
                int src = __shfl_sync(0xffffffffu, nsrc, e);
                float qls = __ldg(g_ql + src);
                const float4* xls = (const float4*)(g_xl + (size_t)src * D);
                float4 a0 = xls[lane], a1 = xls[lane + 32];
                float p;
                p = t0.x * fabsf(a0.x + r0.x);
                p = fmaf(t0.y, fabsf(a0.y + r0.y), p);
                p = fmaf(t0.z, fabsf(a0.z + r0.z), p);
                p = fmaf(t0.w, fabsf(a0.w + r0.w), p);
                p = fmaf(t1.x, fabsf(a1.x + r1.x), p);
                p = fmaf(t1.y, fabsf(a1.y + r1.y), p);
                p = fmaf(t1.z, fabsf(a1.z + r1.z), p);
                p = fmaf(t1.w, fabsf(a1.w + r1.w), p);
#pragma unroll
                for (int o = 16; o; o >>= 1) p += __shfl_xor_sync(0xffffffffu, p, o);
                float ev = __expf(fmaf(0.4f, p, 0.6f * (qls + qrd)));
                den += ev;
                acc0.x = fmaf(ev, a0.x, acc0.x); acc0.y = fmaf(ev, a0.y, acc0.y);
                acc0.z = fmaf(ev, a0.z, acc0.z); acc0.w = fmaf(ev, a0.w, acc0.w);
                acc1.x = fmaf(ev, a1.x, acc1.x); acc1.y = fmaf(ev, a1.y, acc1.y);
                acc1.z = fmaf(ev, a1.z, acc1.z); acc1.w = fmaf(ev, a1.w, acc1.w);
            }
        }

        float inv = 1.f / den;
        const float4* dup = (const float4*)(du + (size_t)dst * D);
        float4 u0 = dup[lane], u1 = dup[lane + 32];
        const float4* bp = (const float4*)bias;
        float4 b0 = bp[lane], b1 = bp[lane + 32];

        float4 v0, v1;
        v0.x = fmaxf(acc0.x * inv + b0.x, 0.f); v0.x = (u0.x >= 0.5f) ? v0.x * 2.f : 0.f;
        v0.y = fmaxf(acc0.y * inv + b0.y, 0.f); v0.y = (u0.y >= 0.5f) ? v0.y * 2.f : 0.f;
        v0.z = fmaxf(acc0.z * inv + b0.z, 0.f); v0.z = (u0.z >= 0.5f) ? v0.z * 2.f : 0.f;
        v0.w = fmaxf(acc0.w * inv + b0.w, 0.f); v0.w = (u0.w >= 0.5f) ? v0.w * 2.f : 0.f;
        v1.x = fmaxf(acc1.x * inv + b1.x, 0.f); v1.x = (u1.x >= 0.5f) ? v1.x * 2.f : 0.f;
        v1.y = fmaxf(acc1.y * inv + b1.y, 0.f); v1.y = (u1.y >= 0.5f) ? v1.y * 2.f : 0.f;
        v1.z = fmaxf(acc1.z * inv + b1.z, 0.f); v1.z = (u1.z >= 0.5f) ? v1.z * 2.f : 0.f;
        v1.w = fmaxf(acc1.w * inv + b1.w, 0.f); v1.w = (u1.w >= 0.5f) ? v1.w * 2.f : 0.f;

        float4* op = (float4*)(g_agg + (size_t)dst * D);
        op[lane] = v0; op[lane + 32] = v1;

        int c0 = lane * 4, c1 = 128 + lane * 4;
        atomicAdd(&s_sum[c0 + 0], v0.x); atomicAdd(&s_sq[c0 + 0], v0.x * v0.x);
        atomicAdd(&s_sum[c0 + 1], v0.y); atomicAdd(&s_sq[c0 + 1], v0.y * v0.y);
        atomicAdd(&s_sum[c0 + 2], v0.z); atomicAdd(&s_sq[c0 + 2], v0.z * v0.z);
        atomicAdd(&s_sum[c0 + 3], v0.w); atomicAdd(&s_sq[c0 + 3], v0.w * v0.w);
        atomicAdd(&s_sum[c1 + 0], v1.x); atomicAdd(&s_sq[c1 + 0], v1.x * v1.x);
        atomicAdd(&s_sum[c1 + 1], v1.y); atomicAdd(&s_sq[c1 + 1], v1.y * v1.y);
        atomicAdd(&s_sum[c1 + 2], v1.z); atomicAdd(&s_sq[c1 + 2], v1.z * v1.z);
        atomicAdd(&s_sum[c1 + 3], v1.w); atomicAdd(&s_sq[c1 + 3], v1.w * v1.w);
    }
    __syncthreads();
    atomicAdd(&g_colsum[tid], s_sum[tid]);
    atomicAdd(&g_colsumsq[tid], s_sq[tid]);
}

// ---------------- final BN normalize --------------------------------
__global__ void k_bnnorm(const float* __restrict__ gamma, const float* __restrict__ beta,
                         float* __restrict__ out, int N) {
    int d = threadIdx.x;
    float invN = 1.f / (float)N;
    float mean = g_colsum[d] * invN;
    float var = g_colsumsq[d] * invN - mean * mean;
    float inv = rsqrtf(var + 1e-5f);
    float ga = gamma[d], be = beta[d];
    for (int r = blockIdx.x; r < N; r += gridDim.x) {
        out[(size_t)r * D + d] = ga * (g_agg[(size_t)r * D + d] - mean) * inv + be;
    }
}

// ---------------- launch ---------------------------------------------
extern "C" void kernel_launch(void* const* d_in, const int* in_sizes, int n_in,
                              void* d_out, int out_size) {
    (void)n_in; (void)out_size;
    const float* x     = (const float*)d_in[0];
    const void*  ei    = d_in[1];
    const float* Wl    = (const float*)d_in[2];
    const float* bl    = (const float*)d_in[3];
    const float* Wr    = (const float*)d_in[4];
    const float* br    = (const float*)d_in[5];
    const float* att   = (const float*)d_in[6];
    const float* bias  = (const float*)d_in[7];
    const float* gamma = (const float*)d_in[8];
    const float* beta  = (const float*)d_in[9];
    const float* du    = (const float*)d_in[10];

    int N = in_sizes[0] / D;
    int E = in_sizes[1] / 2;
    int mrows = (N + 127) / 128;
    int NPAD = mrows * 128;

    const int SMEM_MMA = 2 * STG;   // 221184 bytes
    static cudaStream_t s2 = nullptr;
    static cudaEvent_t evFork = nullptr, evJoin = nullptr;
    if (!s2) {
        cudaFuncSetAttribute(k_hmma, cudaFuncAttributeMaxDynamicSharedMemorySize, SMEM_MMA);
        cudaStreamCreateWithFlags(&s2, cudaStreamNonBlocking);
        cudaEventCreateWithFlags(&evFork, cudaEventDisableTiming);
        cudaEventCreateWithFlags(&evJoin, cudaEventDisableTiming);
    }

    // ---- fork: CSR chain on s2, conv+GEMM chain on main ----
    cudaEventRecord(evFork, 0);
    cudaStreamWaitEvent(s2, evFork, 0);

    k_init<<<40, 256, 0, s2>>>((const long long*)ei, E, N);
    k_count<<<(E / 2 + 256) / 256, 256, 0, s2>>>(ei, E);
    k_alloc<<<(N + 255) / 256, 256, 0, s2>>>(N);
    k_fill<<<(E / 2 + 256) / 256, 256, 0, s2>>>(ei, E);
    cudaEventRecord(evJoin, s2);

    int xblocks = (NPAD * (D / 4) + 255) / 256;
    k_conv<<<128 + xblocks, 256>>>(x, Wl, Wr, N, NPAD);
    dim3 gg(2, mrows);
    k_hmma<<<gg, 512, SMEM_MMA>>>(bl, br, att, N);

    // ---- join ----
    cudaStreamWaitEvent(0, evJoin, 0);

    // dst-centric aggregation + epilogue + BN stats
    k_agg<<<(N + 7) / 8, 256>>>(att, bias, du, N);

    // BN normalize
    k_bnnorm<<<512, 256>>>(gamma, beta, (float*)d_out, N);
}